// round 1
// baseline (speedup 1.0000x reference)
#include <cuda_runtime.h>
#include <cstdint>

#define NN   50000
#define EE   800000
#define ETOT (EE + NN)
#define F1   256      // HEADS*HID
#define HEADS 8
#define FULLMASK 0xffffffffu

// ---------------- device scratch (no allocations allowed) ----------------
__device__ float  g_h1[NN * F1];      // layer1 projection  [N,8,32]
__device__ float  g_out1[NN * F1];    // elu(aggregated)    [N,256]
__device__ float  g_as1[NN * HEADS];
__device__ float  g_ad1[NN * HEADS];
__device__ float4 g_node2[NN];        // (z0, z1, a_src2, a_dst2)
__device__ int    g_counts[NN];
__device__ int    g_off[NN + 1];
__device__ int    g_cursor[NN];
__device__ int    g_csr[ETOT];        // src node per edge, grouped by dst
__device__ int    g_is32;             // 1 if edge_index is int32

// ---------------- dtype detection for edge_index ----------------
__global__ void detect_kernel(const long long* __restrict__ ei) {
    // If data is really int32 node-ids, reading as int64 combines two ids:
    // v = lo + (hi<<32); any nonzero hi makes v >= 2^32 >> NN.
    if (threadIdx.x == 0) g_is32 = 0;
    __syncthreads();
    int bad = 0;
    for (int i = threadIdx.x; i < 1024; i += blockDim.x) {
        long long v = ei[i];
        if (v < 0 || v >= (long long)NN) bad = 1;
    }
    if (__syncthreads_or(bad)) { if (threadIdx.x == 0) g_is32 = 1; }
}

// ---------------- CSR build ----------------
__global__ void init_kernel() {
    int i = blockIdx.x * blockDim.x + threadIdx.x;
    if (i < NN) { g_counts[i] = 1; g_cursor[i] = 0; }  // 1 = self loop
}

__global__ void hist_kernel(const void* __restrict__ eiv) {
    int i = blockIdx.x * blockDim.x + threadIdx.x;
    if (i >= EE) return;
    int d;
    if (g_is32) d = ((const int*)eiv)[EE + i];
    else        d = (int)((const long long*)eiv)[EE + i];
    atomicAdd(&g_counts[d], 1);
}

__global__ void scan_kernel() {   // single block, 1024 threads
    __shared__ int sw[32];
    int tid = threadIdx.x, lane = tid & 31, wid = tid >> 5;
    int carry = 0;
    for (int base = 0; base < NN; base += 1024) {
        int idx = base + tid;
        int v = (idx < NN) ? g_counts[idx] : 0;
        int x = v;
        #pragma unroll
        for (int o = 1; o < 32; o <<= 1) {
            int n = __shfl_up_sync(FULLMASK, x, o);
            if (lane >= o) x += n;
        }
        if (lane == 31) sw[wid] = x;
        __syncthreads();
        if (wid == 0) {
            int y = sw[lane];
            #pragma unroll
            for (int o = 1; o < 32; o <<= 1) {
                int n = __shfl_up_sync(FULLMASK, y, o);
                if (lane >= o) y += n;
            }
            sw[lane] = y;
        }
        __syncthreads();
        int wpre = wid ? sw[wid - 1] : 0;
        int excl = carry + wpre + x - v;
        if (idx < NN)     g_off[idx] = excl;
        if (idx == NN - 1) g_off[NN] = excl + v;
        carry += sw[31];
        __syncthreads();
    }
}

__global__ void scatter_kernel(const void* __restrict__ eiv) {
    int i = blockIdx.x * blockDim.x + threadIdx.x;
    if (i < EE) {
        int s, d;
        if (g_is32) { s = ((const int*)eiv)[i]; d = ((const int*)eiv)[EE + i]; }
        else { s = (int)((const long long*)eiv)[i]; d = (int)((const long long*)eiv)[EE + i]; }
        int pos = g_off[d] + atomicAdd(&g_cursor[d], 1);
        g_csr[pos] = s;
    } else if (i < ETOT) {
        int n = i - EE;
        int pos = g_off[n] + atomicAdd(&g_cursor[n], 1);
        g_csr[pos] = n;  // self loop
    }
}

// ---------------- layer 1 GEMM: h1 = x @ W1 ----------------
// BM=64 rows, all 256 cols, K chunked by 32. 256 threads, 4x16 register tile.
__global__ void gemm1_kernel(const float* __restrict__ x, const float* __restrict__ W) {
    __shared__ float xs[64][32];
    __shared__ float ws[32][256];
    int tid = threadIdx.x;
    int row0 = blockIdx.x * 64;
    int tx = tid & 15, ty = tid >> 4;
    float acc[4][16];
    #pragma unroll
    for (int i = 0; i < 4; i++)
        #pragma unroll
        for (int j = 0; j < 16; j++) acc[i][j] = 0.f;

    for (int k0 = 0; k0 < 128; k0 += 32) {
        #pragma unroll
        for (int i = 0; i < 8; i++) {
            int f = tid + i * 256; int r = f >> 5, c = f & 31;
            int gr = row0 + r;
            xs[r][c] = (gr < NN) ? x[gr * 128 + k0 + c] : 0.f;
        }
        #pragma unroll
        for (int i = 0; i < 32; i++) {
            int f = tid + i * 256; int r = f >> 8, c = f & 255;
            ws[r][c] = W[(k0 + r) * 256 + c];
        }
        __syncthreads();
        #pragma unroll
        for (int kk = 0; kk < 32; kk++) {
            float a[4];
            #pragma unroll
            for (int i = 0; i < 4; i++) a[i] = xs[ty * 4 + i][kk];
            float4 b[4];
            #pragma unroll
            for (int j = 0; j < 4; j++)
                b[j] = *(const float4*)&ws[kk][tx * 4 + j * 64];
            #pragma unroll
            for (int i = 0; i < 4; i++) {
                #pragma unroll
                for (int j = 0; j < 4; j++) {
                    acc[i][j*4+0] += a[i] * b[j].x;
                    acc[i][j*4+1] += a[i] * b[j].y;
                    acc[i][j*4+2] += a[i] * b[j].z;
                    acc[i][j*4+3] += a[i] * b[j].w;
                }
            }
        }
        __syncthreads();
    }
    #pragma unroll
    for (int i = 0; i < 4; i++) {
        int r = row0 + ty * 4 + i;
        if (r < NN) {
            #pragma unroll
            for (int j = 0; j < 4; j++) {
                float4 o = make_float4(acc[i][j*4], acc[i][j*4+1], acc[i][j*4+2], acc[i][j*4+3]);
                *(float4*)&g_h1[r * 256 + tx * 4 + j * 64] = o;
            }
        }
    }
}

// ---------------- layer 1 attention dot products (warp per node) ----------------
__global__ void att1_kernel(const float* __restrict__ asrc, const float* __restrict__ adst) {
    int w = (blockIdx.x * blockDim.x + threadIdx.x) >> 5;
    int lane = threadIdx.x & 31;
    if (w >= NN) return;
    const float4* hn = (const float4*)(g_h1 + w * 256);
    float4 v0 = hn[lane], v1 = hn[32 + lane];
    const float4* s4 = (const float4*)asrc;
    const float4* d4 = (const float4*)adst;
    float4 s0 = s4[lane], s1 = s4[32 + lane];
    float4 d0 = d4[lane], d1 = d4[32 + lane];
    float ps0 = v0.x*s0.x + v0.y*s0.y + v0.z*s0.z + v0.w*s0.w;
    float ps1 = v1.x*s1.x + v1.y*s1.y + v1.z*s1.z + v1.w*s1.w;
    float pd0 = v0.x*d0.x + v0.y*d0.y + v0.z*d0.z + v0.w*d0.w;
    float pd1 = v1.x*d1.x + v1.y*d1.y + v1.z*d1.z + v1.w*d1.w;
    #pragma unroll
    for (int o = 1; o < 8; o <<= 1) {
        ps0 += __shfl_xor_sync(FULLMASK, ps0, o);
        ps1 += __shfl_xor_sync(FULLMASK, ps1, o);
        pd0 += __shfl_xor_sync(FULLMASK, pd0, o);
        pd1 += __shfl_xor_sync(FULLMASK, pd1, o);
    }
    if ((lane & 7) == 0) {
        int h = lane >> 3;
        g_as1[w * 8 + h]     = ps0;
        g_as1[w * 8 + 4 + h] = ps1;
        g_ad1[w * 8 + h]     = pd0;
        g_ad1[w * 8 + 4 + h] = pd1;
    }
}

// ---------------- layer 1 aggregation + softmax + bias + ELU (warp per dst) -------
__global__ void agg1_kernel(const float* __restrict__ b1) {
    int w = (blockIdx.x * blockDim.x + threadIdx.x) >> 5;
    int lane = threadIdx.x & 31;
    if (w >= NN) return;
    float ad = (lane < 8) ? g_ad1[w * 8 + lane] : 0.f;
    int beg = g_off[w], end = g_off[w + 1];
    float4 acc0 = make_float4(0,0,0,0), acc1 = make_float4(0,0,0,0);
    float denomL = 0.f;
    int h0 = lane >> 3;
    for (int e = beg; e < end; e++) {
        int s = g_csr[e];
        float p = 0.f;
        if (lane < 8) {
            float t = g_as1[s * 8 + lane] + ad;
            t = t > 0.f ? t : 0.2f * t;      // leaky relu
            p = __expf(t);
            denomL += p;
        }
        const float4* hs = (const float4*)(g_h1 + s * 256);
        float4 v0 = hs[lane], v1 = hs[32 + lane];
        float p0 = __shfl_sync(FULLMASK, p, h0);
        float p1 = __shfl_sync(FULLMASK, p, h0 + 4);
        acc0.x += p0 * v0.x; acc0.y += p0 * v0.y; acc0.z += p0 * v0.z; acc0.w += p0 * v0.w;
        acc1.x += p1 * v1.x; acc1.y += p1 * v1.y; acc1.z += p1 * v1.z; acc1.w += p1 * v1.w;
    }
    float inv0 = 1.f / __shfl_sync(FULLMASK, denomL, h0);
    float inv1 = 1.f / __shfl_sync(FULLMASK, denomL, h0 + 4);
    const float4* b4 = (const float4*)b1;
    float4 bb0 = b4[lane], bb1 = b4[32 + lane];
    float4 o0, o1;
    o0.x = acc0.x * inv0 + bb0.x;  o0.y = acc0.y * inv0 + bb0.y;
    o0.z = acc0.z * inv0 + bb0.z;  o0.w = acc0.w * inv0 + bb0.w;
    o1.x = acc1.x * inv1 + bb1.x;  o1.y = acc1.y * inv1 + bb1.y;
    o1.z = acc1.z * inv1 + bb1.z;  o1.w = acc1.w * inv1 + bb1.w;
    // ELU
    o0.x = o0.x > 0.f ? o0.x : expm1f(o0.x);
    o0.y = o0.y > 0.f ? o0.y : expm1f(o0.y);
    o0.z = o0.z > 0.f ? o0.z : expm1f(o0.z);
    o0.w = o0.w > 0.f ? o0.w : expm1f(o0.w);
    o1.x = o1.x > 0.f ? o1.x : expm1f(o1.x);
    o1.y = o1.y > 0.f ? o1.y : expm1f(o1.y);
    o1.z = o1.z > 0.f ? o1.z : expm1f(o1.z);
    o1.w = o1.w > 0.f ? o1.w : expm1f(o1.w);
    float4* outp = (float4*)(g_out1 + w * 256);
    outp[lane] = o0;
    outp[32 + lane] = o1;
}

// ---------------- layer 2 projection + attention scalars (warp per node) ---------
__global__ void proj2_kernel(const float* __restrict__ W2,
                             const float* __restrict__ as2,
                             const float* __restrict__ ad2v) {
    int w = (blockIdx.x * blockDim.x + threadIdx.x) >> 5;
    int lane = threadIdx.x & 31;
    if (w >= NN) return;
    const float4* hn = (const float4*)(g_out1 + w * 256);
    float4 v0 = hn[lane], v1 = hn[32 + lane];
    const float4* w4 = (const float4*)W2;   // W2[256][2]
    float4 wa0 = w4[lane * 2],       wb0 = w4[lane * 2 + 1];
    float4 wa1 = w4[(32+lane) * 2],  wb1 = w4[(32+lane) * 2 + 1];
    float s0 = v0.x*wa0.x + v0.y*wa0.z + v0.z*wb0.x + v0.w*wb0.z
             + v1.x*wa1.x + v1.y*wa1.z + v1.z*wb1.x + v1.w*wb1.z;
    float s1 = v0.x*wa0.y + v0.y*wa0.w + v0.z*wb0.y + v0.w*wb0.w
             + v1.x*wa1.y + v1.y*wa1.w + v1.z*wb1.y + v1.w*wb1.w;
    #pragma unroll
    for (int o = 16; o >= 1; o >>= 1) {
        s0 += __shfl_xor_sync(FULLMASK, s0, o);
        s1 += __shfl_xor_sync(FULLMASK, s1, o);
    }
    if (lane == 0) {
        float a = s0 * as2[0] + s1 * as2[1];
        float d = s0 * ad2v[0] + s1 * ad2v[1];
        g_node2[w] = make_float4(s0, s1, a, d);
    }
}

// ---------------- layer 2 aggregation + bias + log_softmax (warp per dst) --------
__global__ void agg2_kernel(const float* __restrict__ b2, float* __restrict__ out) {
    int w = (blockIdx.x * blockDim.x + threadIdx.x) >> 5;
    int lane = threadIdx.x & 31;
    if (w >= NN) return;
    float ad = g_node2[w].w;
    int beg = g_off[w], end = g_off[w + 1];
    float sp = 0.f, s0 = 0.f, s1 = 0.f;
    for (int e = beg + lane; e < end; e += 32) {
        int s = g_csr[e];
        float4 v = g_node2[s];
        float t = v.z + ad;
        t = t > 0.f ? t : 0.2f * t;
        float p = __expf(t);
        sp += p; s0 += p * v.x; s1 += p * v.y;
    }
    #pragma unroll
    for (int o = 16; o >= 1; o >>= 1) {
        sp += __shfl_xor_sync(FULLMASK, sp, o);
        s0 += __shfl_xor_sync(FULLMASK, s0, o);
        s1 += __shfl_xor_sync(FULLMASK, s1, o);
    }
    if (lane == 0) {
        float z0 = s0 / sp + b2[0];
        float z1 = s1 / sp + b2[1];
        float m = fmaxf(z0, z1);
        float l = m + logf(expf(z0 - m) + expf(z1 - m));
        out[w * 2 + 0] = z0 - l;
        out[w * 2 + 1] = z1 - l;
    }
}

// ---------------- launch ----------------
extern "C" void kernel_launch(void* const* d_in, const int* in_sizes, int n_in,
                              void* d_out, int out_size) {
    const float* x    = (const float*)d_in[0];
    const void*  ei   = d_in[1];               // int64 or int32, detected on device
    const float* W1   = (const float*)d_in[2];
    const float* as1  = (const float*)d_in[3];
    const float* ad1  = (const float*)d_in[4];
    const float* b1   = (const float*)d_in[5];
    const float* W2   = (const float*)d_in[6];
    const float* as2  = (const float*)d_in[7];
    const float* ad2  = (const float*)d_in[8];
    const float* b2   = (const float*)d_in[9];
    float* out = (float*)d_out;

    const int TB = 256;
    detect_kernel<<<1, 256>>>((const long long*)ei);
    init_kernel<<<(NN + TB - 1) / TB, TB>>>();
    hist_kernel<<<(EE + TB - 1) / TB, TB>>>(ei);
    scan_kernel<<<1, 1024>>>();
    scatter_kernel<<<(ETOT + TB - 1) / TB, TB>>>(ei);

    gemm1_kernel<<<(NN + 63) / 64, 256>>>(x, W1);

    int warpBlocks = (NN + 7) / 8;   // 8 warps per 256-thread block
    att1_kernel<<<warpBlocks, TB>>>(as1, ad1);
    agg1_kernel<<<warpBlocks, TB>>>(b1);
    proj2_kernel<<<warpBlocks, TB>>>(W2, as2, ad2);
    agg2_kernel<<<warpBlocks, TB>>>(b2, out);
}

// round 2
// speedup vs baseline: 1.3279x; 1.3279x over previous
#include <cuda_runtime.h>
#include <cuda_bf16.h>
#include <cstdint>

#define NN   50000
#define EE   800000
#define ETOT (EE + NN)
#define F1   256
#define HEADS 8
#define FULLMASK 0xffffffffu
#define SCAN_BLOCKS ((NN + 255) / 256)

// ---------------- device scratch ----------------
__device__ float  g_h1[NN * F1];                 // fp32 projection (for attention dots)
__device__ __nv_bfloat162 g_h1b[NN * (F1 / 2)];  // bf16 copy (for edge gather)
__device__ float  g_out1[NN * F1];
__device__ float  g_as1[NN * HEADS];
__device__ float  g_ad1[NN * HEADS];
__device__ float4 g_node2[NN];
__device__ int    g_counts[NN];
__device__ int    g_off[NN + 1];
__device__ int    g_cursor[NN];
__device__ int    g_csr[ETOT];
__device__ int    g_bsum[SCAN_BLOCKS];
__device__ int    g_is32;

__device__ __forceinline__ int warp_incl_scan(int x, int lane) {
    #pragma unroll
    for (int o = 1; o < 32; o <<= 1) {
        int n = __shfl_up_sync(FULLMASK, x, o);
        if (lane >= o) x += n;
    }
    return x;
}

// ---------------- dtype detection ----------------
__global__ void detect_kernel(const long long* __restrict__ ei) {
    if (threadIdx.x == 0) g_is32 = 0;
    __syncthreads();
    int bad = 0;
    for (int i = threadIdx.x; i < 1024; i += blockDim.x) {
        long long v = ei[i];
        if (v < 0 || v >= (long long)NN) bad = 1;
    }
    if (__syncthreads_or(bad)) { if (threadIdx.x == 0) g_is32 = 1; }
}

// ---------------- CSR build ----------------
__global__ void init_kernel() {
    int i = blockIdx.x * blockDim.x + threadIdx.x;
    if (i < NN) { g_counts[i] = 1; g_cursor[i] = 0; }
}

__global__ void hist_kernel(const void* __restrict__ eiv) {
    int i = blockIdx.x * blockDim.x + threadIdx.x;
    if (i >= EE) return;
    int d;
    if (g_is32) d = ((const int*)eiv)[EE + i];
    else        d = (int)((const long long*)eiv)[EE + i];
    atomicAdd(&g_counts[d], 1);
}

// multi-block scan: stage 1 (local exclusive scan + block sums)
__global__ void scan1_kernel() {
    __shared__ int sw[8];
    int tid = threadIdx.x, lane = tid & 31, wid = tid >> 5;
    int idx = blockIdx.x * 256 + tid;
    int v = (idx < NN) ? g_counts[idx] : 0;
    int x = warp_incl_scan(v, lane);
    if (lane == 31) sw[wid] = x;
    __syncthreads();
    if (wid == 0) {
        int y = (lane < 8) ? sw[lane] : 0;
        #pragma unroll
        for (int o = 1; o < 8; o <<= 1) {
            int n = __shfl_up_sync(FULLMASK, y, o);
            if (lane >= o) y += n;
        }
        if (lane < 8) sw[lane] = y;
    }
    __syncthreads();
    int pre = wid ? sw[wid - 1] : 0;
    if (idx < NN) g_off[idx] = pre + x - v;
    if (tid == 255) g_bsum[blockIdx.x] = pre + x;
}

// stage 2: exclusive scan of block sums (single block)
__global__ void scan2_kernel() {
    __shared__ int sw[8];
    int tid = threadIdx.x, lane = tid & 31, wid = tid >> 5;
    int v = (tid < SCAN_BLOCKS) ? g_bsum[tid] : 0;
    int x = warp_incl_scan(v, lane);
    if (lane == 31) sw[wid] = x;
    __syncthreads();
    if (wid == 0) {
        int y = (lane < 8) ? sw[lane] : 0;
        #pragma unroll
        for (int o = 1; o < 8; o <<= 1) {
            int n = __shfl_up_sync(FULLMASK, y, o);
            if (lane >= o) y += n;
        }
        if (lane < 8) sw[lane] = y;
    }
    __syncthreads();
    int pre = wid ? sw[wid - 1] : 0;
    if (tid < SCAN_BLOCKS) g_bsum[tid] = pre + x - v;
}

// stage 3: add block offsets
__global__ void scan3_kernel() {
    int idx = blockIdx.x * 256 + threadIdx.x;
    int add = g_bsum[blockIdx.x];
    if (idx < NN) g_off[idx] += add;
    if (idx == 0) g_off[NN] = ETOT;
}

__global__ void scatter_kernel(const void* __restrict__ eiv) {
    int i = blockIdx.x * blockDim.x + threadIdx.x;
    if (i < EE) {
        int s, d;
        if (g_is32) { s = ((const int*)eiv)[i]; d = ((const int*)eiv)[EE + i]; }
        else { s = (int)((const long long*)eiv)[i]; d = (int)((const long long*)eiv)[EE + i]; }
        int pos = g_off[d] + atomicAdd(&g_cursor[d], 1);
        g_csr[pos] = s;
    } else if (i < ETOT) {
        int n = i - EE;
        int pos = g_off[n] + atomicAdd(&g_cursor[n], 1);
        g_csr[pos] = n;
    }
}

// ---------------- layer1 GEMM via tf32 mma.sync (m16n8k8) ----------------
// Block: 256 thr (8 warps, 2x4), tile BM=64 x BN=256, K chunked by 32.
#define XS_STRIDE 36
#define WS_STRIDE 264
__global__ void __launch_bounds__(256) gemm1_kernel(const float* __restrict__ x,
                                                    const float* __restrict__ W) {
    __shared__ unsigned xs[64 * XS_STRIDE];
    __shared__ unsigned ws[32 * WS_STRIDE];
    int tid = threadIdx.x;
    int lane = tid & 31, wid = tid >> 5;
    int wm = wid >> 2, wn = wid & 3;       // warp tile 32x64
    int g = lane >> 2, tig = lane & 3;     // mma groupID / thread-in-group
    int row0 = blockIdx.x * 64;

    float acc[2][8][4];
    #pragma unroll
    for (int mi = 0; mi < 2; mi++)
        #pragma unroll
        for (int ni = 0; ni < 8; ni++)
            #pragma unroll
            for (int q = 0; q < 4; q++) acc[mi][ni][q] = 0.f;

    for (int kc = 0; kc < 128; kc += 32) {
        #pragma unroll
        for (int i = 0; i < 8; i++) {
            int t = tid + i * 256; int r = t >> 5, c = t & 31;
            int gr = row0 + r;
            float v = (gr < NN) ? x[gr * 128 + kc + c] : 0.f;
            unsigned u; asm("cvt.rna.tf32.f32 %0, %1;" : "=r"(u) : "f"(v));
            xs[r * XS_STRIDE + c] = u;
        }
        #pragma unroll
        for (int i = 0; i < 32; i++) {
            float v = W[(kc + i) * 256 + tid];
            unsigned u; asm("cvt.rna.tf32.f32 %0, %1;" : "=r"(u) : "f"(v));
            ws[i * WS_STRIDE + tid] = u;
        }
        __syncthreads();
        #pragma unroll
        for (int kk = 0; kk < 32; kk += 8) {
            unsigned a[2][4];
            #pragma unroll
            for (int mi = 0; mi < 2; mi++) {
                int rb = wm * 32 + mi * 16;
                a[mi][0] = xs[(rb + g) * XS_STRIDE + kk + tig];
                a[mi][1] = xs[(rb + g + 8) * XS_STRIDE + kk + tig];
                a[mi][2] = xs[(rb + g) * XS_STRIDE + kk + tig + 4];
                a[mi][3] = xs[(rb + g + 8) * XS_STRIDE + kk + tig + 4];
            }
            #pragma unroll
            for (int ni = 0; ni < 8; ni++) {
                int cb = wn * 64 + ni * 8 + g;
                unsigned b0 = ws[(kk + tig) * WS_STRIDE + cb];
                unsigned b1 = ws[(kk + tig + 4) * WS_STRIDE + cb];
                #pragma unroll
                for (int mi = 0; mi < 2; mi++) {
                    asm volatile(
                        "mma.sync.aligned.m16n8k8.row.col.f32.tf32.tf32.f32 "
                        "{%0,%1,%2,%3}, {%4,%5,%6,%7}, {%8,%9}, {%0,%1,%2,%3};"
                        : "+f"(acc[mi][ni][0]), "+f"(acc[mi][ni][1]),
                          "+f"(acc[mi][ni][2]), "+f"(acc[mi][ni][3])
                        : "r"(a[mi][0]), "r"(a[mi][1]), "r"(a[mi][2]), "r"(a[mi][3]),
                          "r"(b0), "r"(b1));
                }
            }
        }
        __syncthreads();
    }
    // epilogue: fp32 + bf16 copies
    #pragma unroll
    for (int mi = 0; mi < 2; mi++) {
        #pragma unroll
        for (int ni = 0; ni < 8; ni++) {
            int r0 = row0 + wm * 32 + mi * 16 + g;
            int c  = wn * 64 + ni * 8 + tig * 2;
            if (r0 < NN) {
                *(float2*)&g_h1[r0 * 256 + c] = make_float2(acc[mi][ni][0], acc[mi][ni][1]);
                g_h1b[r0 * 128 + (c >> 1)] =
                    __float22bfloat162_rn(make_float2(acc[mi][ni][0], acc[mi][ni][1]));
            }
            int r1 = r0 + 8;
            if (r1 < NN) {
                *(float2*)&g_h1[r1 * 256 + c] = make_float2(acc[mi][ni][2], acc[mi][ni][3]);
                g_h1b[r1 * 128 + (c >> 1)] =
                    __float22bfloat162_rn(make_float2(acc[mi][ni][2], acc[mi][ni][3]));
            }
        }
    }
}

// ---------------- layer 1 attention dots (warp per node) ----------------
__global__ void att1_kernel(const float* __restrict__ asrc, const float* __restrict__ adst) {
    int w = (blockIdx.x * blockDim.x + threadIdx.x) >> 5;
    int lane = threadIdx.x & 31;
    if (w >= NN) return;
    const float4* hn = (const float4*)(g_h1 + w * 256);
    float4 v0 = hn[lane], v1 = hn[32 + lane];
    const float4* s4 = (const float4*)asrc;
    const float4* d4 = (const float4*)adst;
    float4 s0 = s4[lane], s1 = s4[32 + lane];
    float4 d0 = d4[lane], d1 = d4[32 + lane];
    float ps0 = v0.x*s0.x + v0.y*s0.y + v0.z*s0.z + v0.w*s0.w;
    float ps1 = v1.x*s1.x + v1.y*s1.y + v1.z*s1.z + v1.w*s1.w;
    float pd0 = v0.x*d0.x + v0.y*d0.y + v0.z*d0.z + v0.w*d0.w;
    float pd1 = v1.x*d1.x + v1.y*d1.y + v1.z*d1.z + v1.w*d1.w;
    #pragma unroll
    for (int o = 1; o < 8; o <<= 1) {
        ps0 += __shfl_xor_sync(FULLMASK, ps0, o);
        ps1 += __shfl_xor_sync(FULLMASK, ps1, o);
        pd0 += __shfl_xor_sync(FULLMASK, pd0, o);
        pd1 += __shfl_xor_sync(FULLMASK, pd1, o);
    }
    if ((lane & 7) == 0) {
        int h = lane >> 3;
        g_as1[w * 8 + h]     = ps0;
        g_as1[w * 8 + 4 + h] = ps1;
        g_ad1[w * 8 + h]     = pd0;
        g_ad1[w * 8 + 4 + h] = pd1;
    }
}

// ---------------- layer 1 aggregation (bf16 gather) ----------------
__global__ void agg1_kernel(const float* __restrict__ b1) {
    int w = (blockIdx.x * blockDim.x + threadIdx.x) >> 5;
    int lane = threadIdx.x & 31;
    if (w >= NN) return;
    float ad = (lane < 8) ? g_ad1[w * 8 + lane] : 0.f;
    int beg = g_off[w], end = g_off[w + 1];
    float4 acc0 = make_float4(0,0,0,0), acc1 = make_float4(0,0,0,0);
    float denomL = 0.f;
    int h0 = lane >> 3;
    for (int e = beg; e < end; e++) {
        int s = g_csr[e];
        float p = 0.f;
        if (lane < 8) {
            float t = g_as1[s * 8 + lane] + ad;
            t = t > 0.f ? t : 0.2f * t;
            p = __expf(t);
            denomL += p;
        }
        const uint2* hb = (const uint2*)(g_h1b + s * 128);
        uint2 u0 = hb[lane], u1 = hb[32 + lane];
        float p0 = __shfl_sync(FULLMASK, p, h0);
        float p1 = __shfl_sync(FULLMASK, p, h0 + 4);
        float2 f00 = __bfloat1622float2(*(__nv_bfloat162*)&u0.x);
        float2 f01 = __bfloat1622float2(*(__nv_bfloat162*)&u0.y);
        float2 f10 = __bfloat1622float2(*(__nv_bfloat162*)&u1.x);
        float2 f11 = __bfloat1622float2(*(__nv_bfloat162*)&u1.y);
        acc0.x += p0 * f00.x; acc0.y += p0 * f00.y; acc0.z += p0 * f01.x; acc0.w += p0 * f01.y;
        acc1.x += p1 * f10.x; acc1.y += p1 * f10.y; acc1.z += p1 * f11.x; acc1.w += p1 * f11.y;
    }
    float inv0 = 1.f / __shfl_sync(FULLMASK, denomL, h0);
    float inv1 = 1.f / __shfl_sync(FULLMASK, denomL, h0 + 4);
    const float4* b4 = (const float4*)b1;
    float4 bb0 = b4[lane], bb1 = b4[32 + lane];
    float4 o0, o1;
    o0.x = acc0.x * inv0 + bb0.x;  o0.y = acc0.y * inv0 + bb0.y;
    o0.z = acc0.z * inv0 + bb0.z;  o0.w = acc0.w * inv0 + bb0.w;
    o1.x = acc1.x * inv1 + bb1.x;  o1.y = acc1.y * inv1 + bb1.y;
    o1.z = acc1.z * inv1 + bb1.z;  o1.w = acc1.w * inv1 + bb1.w;
    o0.x = o0.x > 0.f ? o0.x : expm1f(o0.x);
    o0.y = o0.y > 0.f ? o0.y : expm1f(o0.y);
    o0.z = o0.z > 0.f ? o0.z : expm1f(o0.z);
    o0.w = o0.w > 0.f ? o0.w : expm1f(o0.w);
    o1.x = o1.x > 0.f ? o1.x : expm1f(o1.x);
    o1.y = o1.y > 0.f ? o1.y : expm1f(o1.y);
    o1.z = o1.z > 0.f ? o1.z : expm1f(o1.z);
    o1.w = o1.w > 0.f ? o1.w : expm1f(o1.w);
    float4* outp = (float4*)(g_out1 + w * 256);
    outp[lane] = o0;
    outp[32 + lane] = o1;
}

// ---------------- layer 2 projection (warp per node) ----------------
__global__ void proj2_kernel(const float* __restrict__ W2,
                             const float* __restrict__ as2,
                             const float* __restrict__ ad2v) {
    int w = (blockIdx.x * blockDim.x + threadIdx.x) >> 5;
    int lane = threadIdx.x & 31;
    if (w >= NN) return;
    const float4* hn = (const float4*)(g_out1 + w * 256);
    float4 v0 = hn[lane], v1 = hn[32 + lane];
    const float4* w4 = (const float4*)W2;
    float4 wa0 = w4[lane * 2],       wb0 = w4[lane * 2 + 1];
    float4 wa1 = w4[(32+lane) * 2],  wb1 = w4[(32+lane) * 2 + 1];
    float s0 = v0.x*wa0.x + v0.y*wa0.z + v0.z*wb0.x + v0.w*wb0.z
             + v1.x*wa1.x + v1.y*wa1.z + v1.z*wb1.x + v1.w*wb1.z;
    float s1 = v0.x*wa0.y + v0.y*wa0.w + v0.z*wb0.y + v0.w*wb0.w
             + v1.x*wa1.y + v1.y*wa1.w + v1.z*wb1.y + v1.w*wb1.w;
    #pragma unroll
    for (int o = 16; o >= 1; o >>= 1) {
        s0 += __shfl_xor_sync(FULLMASK, s0, o);
        s1 += __shfl_xor_sync(FULLMASK, s1, o);
    }
    if (lane == 0) {
        float a = s0 * as2[0] + s1 * as2[1];
        float d = s0 * ad2v[0] + s1 * ad2v[1];
        g_node2[w] = make_float4(s0, s1, a, d);
    }
}

// ---------------- layer 2 aggregation + log_softmax ----------------
__global__ void agg2_kernel(const float* __restrict__ b2, float* __restrict__ out) {
    int w = (blockIdx.x * blockDim.x + threadIdx.x) >> 5;
    int lane = threadIdx.x & 31;
    if (w >= NN) return;
    float ad = g_node2[w].w;
    int beg = g_off[w], end = g_off[w + 1];
    float sp = 0.f, s0 = 0.f, s1 = 0.f;
    for (int e = beg + lane; e < end; e += 32) {
        int s = g_csr[e];
        float4 v = g_node2[s];
        float t = v.z + ad;
        t = t > 0.f ? t : 0.2f * t;
        float p = __expf(t);
        sp += p; s0 += p * v.x; s1 += p * v.y;
    }
    #pragma unroll
    for (int o = 16; o >= 1; o >>= 1) {
        sp += __shfl_xor_sync(FULLMASK, sp, o);
        s0 += __shfl_xor_sync(FULLMASK, s0, o);
        s1 += __shfl_xor_sync(FULLMASK, s1, o);
    }
    if (lane == 0) {
        float z0 = s0 / sp + b2[0];
        float z1 = s1 / sp + b2[1];
        float m = fmaxf(z0, z1);
        float l = m + logf(expf(z0 - m) + expf(z1 - m));
        out[w * 2 + 0] = z0 - l;
        out[w * 2 + 1] = z1 - l;
    }
}

// ---------------- launch ----------------
extern "C" void kernel_launch(void* const* d_in, const int* in_sizes, int n_in,
                              void* d_out, int out_size) {
    const float* x    = (const float*)d_in[0];
    const void*  ei   = d_in[1];
    const float* W1   = (const float*)d_in[2];
    const float* as1  = (const float*)d_in[3];
    const float* ad1  = (const float*)d_in[4];
    const float* b1   = (const float*)d_in[5];
    const float* W2   = (const float*)d_in[6];
    const float* as2  = (const float*)d_in[7];
    const float* ad2  = (const float*)d_in[8];
    const float* b2   = (const float*)d_in[9];
    float* out = (float*)d_out;

    const int TB = 256;
    detect_kernel<<<1, 256>>>((const long long*)ei);
    init_kernel<<<(NN + TB - 1) / TB, TB>>>();
    hist_kernel<<<(EE + TB - 1) / TB, TB>>>(ei);
    scan1_kernel<<<SCAN_BLOCKS, 256>>>();
    scan2_kernel<<<1, 256>>>();
    scan3_kernel<<<SCAN_BLOCKS, 256>>>();
    scatter_kernel<<<(ETOT + TB - 1) / TB, TB>>>(ei);

    gemm1_kernel<<<(NN + 63) / 64, 256>>>(x, W1);

    int warpBlocks = (NN + 7) / 8;
    att1_kernel<<<warpBlocks, TB>>>(as1, ad1);
    agg1_kernel<<<warpBlocks, TB>>>(b1);
    proj2_kernel<<<warpBlocks, TB>>>(W2, as2, ad2);
    agg2_kernel<<<warpBlocks, TB>>>(b2, out);
}

// round 3
// speedup vs baseline: 1.6891x; 1.2720x over previous
#include <cuda_runtime.h>
#include <cuda_bf16.h>
#include <cstdint>

#define NN   50000
#define EE   800000
#define ETOT (EE + NN)
#define F1   256
#define HEADS 8
#define FULLMASK 0xffffffffu
#define SCAN_BLOCKS ((NN + 255) / 256)

// ---------------- device scratch ----------------
__device__ __nv_bfloat162 g_h1b[NN * (F1 / 2)];  // bf16 projection (only materialized form)
// permuted attention scalars: flat index node*8 + (h<4 ? 2h : 2(h-4)+1)
// so float2 at [node*8 + 2*h0] = (val[h0], val[h0+4])
__device__ float  g_as1[NN * HEADS];
__device__ float  g_ad1[NN * HEADS];
__device__ float4 g_node2[NN];        // (z0, z1, a_src2, a_dst2)
__device__ int    g_counts[NN];
__device__ int    g_off[NN + 1];
__device__ int    g_cursor[NN];
__device__ int    g_csr[ETOT];
__device__ int    g_bsum[SCAN_BLOCKS];
__device__ int    g_is32;

__device__ __forceinline__ int warp_incl_scan(int x, int lane) {
    #pragma unroll
    for (int o = 1; o < 32; o <<= 1) {
        int n = __shfl_up_sync(FULLMASK, x, o);
        if (lane >= o) x += n;
    }
    return x;
}

// ---------------- dtype detection ----------------
__global__ void detect_kernel(const long long* __restrict__ ei) {
    if (threadIdx.x == 0) g_is32 = 0;
    __syncthreads();
    int bad = 0;
    for (int i = threadIdx.x; i < 1024; i += blockDim.x) {
        long long v = ei[i];
        if (v < 0 || v >= (long long)NN) bad = 1;
    }
    if (__syncthreads_or(bad)) { if (threadIdx.x == 0) g_is32 = 1; }
}

// ---------------- CSR build ----------------
__global__ void init_kernel() {
    int i = blockIdx.x * blockDim.x + threadIdx.x;
    if (i < NN) { g_counts[i] = 1; g_cursor[i] = 0; }
}

__global__ void hist_kernel(const void* __restrict__ eiv) {
    int i = blockIdx.x * blockDim.x + threadIdx.x;
    if (i >= EE) return;
    int d;
    if (g_is32) d = ((const int*)eiv)[EE + i];
    else        d = (int)((const long long*)eiv)[EE + i];
    atomicAdd(&g_counts[d], 1);
}

__global__ void scan1_kernel() {
    __shared__ int sw[8];
    int tid = threadIdx.x, lane = tid & 31, wid = tid >> 5;
    int idx = blockIdx.x * 256 + tid;
    int v = (idx < NN) ? g_counts[idx] : 0;
    int x = warp_incl_scan(v, lane);
    if (lane == 31) sw[wid] = x;
    __syncthreads();
    if (wid == 0) {
        int y = (lane < 8) ? sw[lane] : 0;
        #pragma unroll
        for (int o = 1; o < 8; o <<= 1) {
            int n = __shfl_up_sync(FULLMASK, y, o);
            if (lane >= o) y += n;
        }
        if (lane < 8) sw[lane] = y;
    }
    __syncthreads();
    int pre = wid ? sw[wid - 1] : 0;
    if (idx < NN) g_off[idx] = pre + x - v;
    if (tid == 255) g_bsum[blockIdx.x] = pre + x;
}

__global__ void scan2_kernel() {
    __shared__ int sw[8];
    int tid = threadIdx.x, lane = tid & 31, wid = tid >> 5;
    int v = (tid < SCAN_BLOCKS) ? g_bsum[tid] : 0;
    int x = warp_incl_scan(v, lane);
    if (lane == 31) sw[wid] = x;
    __syncthreads();
    if (wid == 0) {
        int y = (lane < 8) ? sw[lane] : 0;
        #pragma unroll
        for (int o = 1; o < 8; o <<= 1) {
            int n = __shfl_up_sync(FULLMASK, y, o);
            if (lane >= o) y += n;
        }
        if (lane < 8) sw[lane] = y;
    }
    __syncthreads();
    int pre = wid ? sw[wid - 1] : 0;
    if (tid < SCAN_BLOCKS) g_bsum[tid] = pre + x - v;
}

__global__ void scan3_kernel() {
    int idx = blockIdx.x * 256 + threadIdx.x;
    int add = g_bsum[blockIdx.x];
    if (idx < NN) g_off[idx] += add;
    if (idx == 0) g_off[NN] = ETOT;
}

__global__ void scatter_kernel(const void* __restrict__ eiv) {
    int i = blockIdx.x * blockDim.x + threadIdx.x;
    if (i < EE) {
        int s, d;
        if (g_is32) { s = ((const int*)eiv)[i]; d = ((const int*)eiv)[EE + i]; }
        else { s = (int)((const long long*)eiv)[i]; d = (int)((const long long*)eiv)[EE + i]; }
        int pos = g_off[d] + atomicAdd(&g_cursor[d], 1);
        g_csr[pos] = s;
    } else if (i < ETOT) {
        int n = i - EE;
        int pos = g_off[n] + atomicAdd(&g_cursor[n], 1);
        g_csr[pos] = n;
    }
}

// ---------------- layer1: tf32 GEMM + fused attention dots, bf16 output ----------
#define XS_STRIDE 36
#define WS_STRIDE 264
__global__ void __launch_bounds__(256) gemm1_kernel(const float* __restrict__ x,
                                                    const float* __restrict__ W,
                                                    const float* __restrict__ asrc,
                                                    const float* __restrict__ adst) {
    __shared__ unsigned xs[64 * XS_STRIDE];
    __shared__ unsigned ws[32 * WS_STRIDE];
    int tid = threadIdx.x;
    int lane = tid & 31, wid = tid >> 5;
    int wm = wid >> 2, wn = wid & 3;       // warp tile 32(m) x 64(n)
    int g = lane >> 2, tig = lane & 3;
    int row0 = blockIdx.x * 64;

    float acc[2][8][4];
    #pragma unroll
    for (int mi = 0; mi < 2; mi++)
        #pragma unroll
        for (int ni = 0; ni < 8; ni++)
            #pragma unroll
            for (int q = 0; q < 4; q++) acc[mi][ni][q] = 0.f;

    for (int kc = 0; kc < 128; kc += 32) {
        #pragma unroll
        for (int i = 0; i < 8; i++) {
            int t = tid + i * 256; int r = t >> 5, c = t & 31;
            int gr = row0 + r;
            float v = (gr < NN) ? x[gr * 128 + kc + c] : 0.f;
            unsigned u; asm("cvt.rna.tf32.f32 %0, %1;" : "=r"(u) : "f"(v));
            xs[r * XS_STRIDE + c] = u;
        }
        #pragma unroll
        for (int i = 0; i < 32; i++) {
            float v = W[(kc + i) * 256 + tid];
            unsigned u; asm("cvt.rna.tf32.f32 %0, %1;" : "=r"(u) : "f"(v));
            ws[i * WS_STRIDE + tid] = u;
        }
        __syncthreads();
        #pragma unroll
        for (int kk = 0; kk < 32; kk += 8) {
            unsigned a[2][4];
            #pragma unroll
            for (int mi = 0; mi < 2; mi++) {
                int rb = wm * 32 + mi * 16;
                a[mi][0] = xs[(rb + g) * XS_STRIDE + kk + tig];
                a[mi][1] = xs[(rb + g + 8) * XS_STRIDE + kk + tig];
                a[mi][2] = xs[(rb + g) * XS_STRIDE + kk + tig + 4];
                a[mi][3] = xs[(rb + g + 8) * XS_STRIDE + kk + tig + 4];
            }
            #pragma unroll
            for (int ni = 0; ni < 8; ni++) {
                int cb = wn * 64 + ni * 8 + g;
                unsigned b0 = ws[(kk + tig) * WS_STRIDE + cb];
                unsigned b1 = ws[(kk + tig + 4) * WS_STRIDE + cb];
                #pragma unroll
                for (int mi = 0; mi < 2; mi++) {
                    asm volatile(
                        "mma.sync.aligned.m16n8k8.row.col.f32.tf32.tf32.f32 "
                        "{%0,%1,%2,%3}, {%4,%5,%6,%7}, {%8,%9}, {%0,%1,%2,%3};"
                        : "+f"(acc[mi][ni][0]), "+f"(acc[mi][ni][1]),
                          "+f"(acc[mi][ni][2]), "+f"(acc[mi][ni][3])
                        : "r"(a[mi][0]), "r"(a[mi][1]), "r"(a[mi][2]), "r"(a[mi][3]),
                          "r"(b0), "r"(b1));
                }
            }
        }
        __syncthreads();
    }

    // ---- fused epilogue: bf16 store + attention partial dots ----
    // pr[mi][ab][hi][sd]: row (mi,ab), head-local hi (ni<4 ? 0 : 1), sd 0=src 1=dst
    float pr[2][2][2][2];
    #pragma unroll
    for (int a0 = 0; a0 < 2; a0++)
        #pragma unroll
        for (int a1 = 0; a1 < 2; a1++)
            #pragma unroll
            for (int a2 = 0; a2 < 2; a2++)
                #pragma unroll
                for (int a3 = 0; a3 < 2; a3++) pr[a0][a1][a2][a3] = 0.f;

    #pragma unroll
    for (int ni = 0; ni < 8; ni++) {
        int c = wn * 64 + ni * 8 + tig * 2;
        float av0 = asrc[c], av1 = asrc[c + 1];
        float dv0 = adst[c], dv1 = adst[c + 1];
        int hi = ni >> 2;
        #pragma unroll
        for (int mi = 0; mi < 2; mi++) {
            pr[mi][0][hi][0] += acc[mi][ni][0] * av0 + acc[mi][ni][1] * av1;
            pr[mi][0][hi][1] += acc[mi][ni][0] * dv0 + acc[mi][ni][1] * dv1;
            pr[mi][1][hi][0] += acc[mi][ni][2] * av0 + acc[mi][ni][3] * av1;
            pr[mi][1][hi][1] += acc[mi][ni][2] * dv0 + acc[mi][ni][3] * dv1;

            int r0 = row0 + wm * 32 + mi * 16 + g;
            if (r0 < NN)
                g_h1b[r0 * 128 + (c >> 1)] =
                    __float22bfloat162_rn(make_float2(acc[mi][ni][0], acc[mi][ni][1]));
            int r1 = r0 + 8;
            if (r1 < NN)
                g_h1b[r1 * 128 + (c >> 1)] =
                    __float22bfloat162_rn(make_float2(acc[mi][ni][2], acc[mi][ni][3]));
        }
    }
    // reduce over the 4 lanes sharing each row (tig group: lanes 4g..4g+3)
    #pragma unroll
    for (int mi = 0; mi < 2; mi++)
        #pragma unroll
        for (int ab = 0; ab < 2; ab++)
            #pragma unroll
            for (int hi = 0; hi < 2; hi++)
                #pragma unroll
                for (int sd = 0; sd < 2; sd++) {
                    float v = pr[mi][ab][hi][sd];
                    v += __shfl_xor_sync(FULLMASK, v, 1);
                    v += __shfl_xor_sync(FULLMASK, v, 2);
                    pr[mi][ab][hi][sd] = v;
                }
    if (tig == 0) {
        #pragma unroll
        for (int mi = 0; mi < 2; mi++)
            #pragma unroll
            for (int ab = 0; ab < 2; ab++) {
                int r = row0 + wm * 32 + mi * 16 + ab * 8 + g;
                if (r < NN) {
                    #pragma unroll
                    for (int hi = 0; hi < 2; hi++) {
                        int h = 2 * wn + hi;
                        int p = (h < 4) ? 2 * h : 2 * (h - 4) + 1;   // permuted slot
                        g_as1[r * 8 + p] = pr[mi][ab][hi][0];
                        g_ad1[r * 8 + p] = pr[mi][ab][hi][1];
                    }
                }
            }
    }
}

// ---------------- layer1 aggregation + softmax + bias + ELU + fused proj2 --------
__global__ void __launch_bounds__(256) agg1_kernel(const float* __restrict__ b1,
                                                   const float* __restrict__ W2,
                                                   const float* __restrict__ as2,
                                                   const float* __restrict__ ad2v) {
    int w = (blockIdx.x * blockDim.x + threadIdx.x) >> 5;
    int lane = threadIdx.x & 31;
    if (w >= NN) return;
    int h0 = lane >> 3;
    float2 adv = *(const float2*)&g_ad1[w * 8 + 2 * h0];   // (ad[h0], ad[h0+4])
    int beg = g_off[w], end = g_off[w + 1];
    float4 acc0 = make_float4(0,0,0,0), acc1 = make_float4(0,0,0,0);
    float den0 = 0.f, den1 = 0.f;

    int e = beg;
    for (; e + 1 < end; e += 2) {
        int sA = g_csr[e], sB = g_csr[e + 1];
        float2 asA = *(const float2*)&g_as1[sA * 8 + 2 * h0];
        float2 asB = *(const float2*)&g_as1[sB * 8 + 2 * h0];
        const uint2* hA = (const uint2*)(g_h1b + sA * 128);
        const uint2* hB = (const uint2*)(g_h1b + sB * 128);
        uint2 uA0 = hA[lane], uA1 = hA[32 + lane];
        uint2 uB0 = hB[lane], uB1 = hB[32 + lane];

        float tA0 = asA.x + adv.x; tA0 = tA0 > 0.f ? tA0 : 0.2f * tA0;
        float tA1 = asA.y + adv.y; tA1 = tA1 > 0.f ? tA1 : 0.2f * tA1;
        float tB0 = asB.x + adv.x; tB0 = tB0 > 0.f ? tB0 : 0.2f * tB0;
        float tB1 = asB.y + adv.y; tB1 = tB1 > 0.f ? tB1 : 0.2f * tB1;
        float pA0 = __expf(tA0), pA1 = __expf(tA1);
        float pB0 = __expf(tB0), pB1 = __expf(tB1);
        den0 += pA0 + pB0; den1 += pA1 + pB1;

        float2 fA00 = __bfloat1622float2(*(__nv_bfloat162*)&uA0.x);
        float2 fA01 = __bfloat1622float2(*(__nv_bfloat162*)&uA0.y);
        float2 fA10 = __bfloat1622float2(*(__nv_bfloat162*)&uA1.x);
        float2 fA11 = __bfloat1622float2(*(__nv_bfloat162*)&uA1.y);
        acc0.x += pA0 * fA00.x; acc0.y += pA0 * fA00.y; acc0.z += pA0 * fA01.x; acc0.w += pA0 * fA01.y;
        acc1.x += pA1 * fA10.x; acc1.y += pA1 * fA10.y; acc1.z += pA1 * fA11.x; acc1.w += pA1 * fA11.y;

        float2 fB00 = __bfloat1622float2(*(__nv_bfloat162*)&uB0.x);
        float2 fB01 = __bfloat1622float2(*(__nv_bfloat162*)&uB0.y);
        float2 fB10 = __bfloat1622float2(*(__nv_bfloat162*)&uB1.x);
        float2 fB11 = __bfloat1622float2(*(__nv_bfloat162*)&uB1.y);
        acc0.x += pB0 * fB00.x; acc0.y += pB0 * fB00.y; acc0.z += pB0 * fB01.x; acc0.w += pB0 * fB01.y;
        acc1.x += pB1 * fB10.x; acc1.y += pB1 * fB10.y; acc1.z += pB1 * fB11.x; acc1.w += pB1 * fB11.y;
    }
    if (e < end) {
        int s = g_csr[e];
        float2 asv = *(const float2*)&g_as1[s * 8 + 2 * h0];
        const uint2* hb = (const uint2*)(g_h1b + s * 128);
        uint2 u0 = hb[lane], u1 = hb[32 + lane];
        float t0 = asv.x + adv.x; t0 = t0 > 0.f ? t0 : 0.2f * t0;
        float t1 = asv.y + adv.y; t1 = t1 > 0.f ? t1 : 0.2f * t1;
        float p0 = __expf(t0), p1 = __expf(t1);
        den0 += p0; den1 += p1;
        float2 f00 = __bfloat1622float2(*(__nv_bfloat162*)&u0.x);
        float2 f01 = __bfloat1622float2(*(__nv_bfloat162*)&u0.y);
        float2 f10 = __bfloat1622float2(*(__nv_bfloat162*)&u1.x);
        float2 f11 = __bfloat1622float2(*(__nv_bfloat162*)&u1.y);
        acc0.x += p0 * f00.x; acc0.y += p0 * f00.y; acc0.z += p0 * f01.x; acc0.w += p0 * f01.y;
        acc1.x += p1 * f10.x; acc1.y += p1 * f10.y; acc1.z += p1 * f11.x; acc1.w += p1 * f11.y;
    }

    float inv0 = 1.f / den0, inv1 = 1.f / den1;
    const float4* b4 = (const float4*)b1;
    float4 bb0 = b4[lane], bb1 = b4[32 + lane];
    float4 o0, o1;
    o0.x = acc0.x * inv0 + bb0.x;  o0.y = acc0.y * inv0 + bb0.y;
    o0.z = acc0.z * inv0 + bb0.z;  o0.w = acc0.w * inv0 + bb0.w;
    o1.x = acc1.x * inv1 + bb1.x;  o1.y = acc1.y * inv1 + bb1.y;
    o1.z = acc1.z * inv1 + bb1.z;  o1.w = acc1.w * inv1 + bb1.w;
    o0.x = o0.x > 0.f ? o0.x : expm1f(o0.x);
    o0.y = o0.y > 0.f ? o0.y : expm1f(o0.y);
    o0.z = o0.z > 0.f ? o0.z : expm1f(o0.z);
    o0.w = o0.w > 0.f ? o0.w : expm1f(o0.w);
    o1.x = o1.x > 0.f ? o1.x : expm1f(o1.x);
    o1.y = o1.y > 0.f ? o1.y : expm1f(o1.y);
    o1.z = o1.z > 0.f ? o1.z : expm1f(o1.z);
    o1.w = o1.w > 0.f ? o1.w : expm1f(o1.w);

    // ---- fused layer-2 projection (was proj2_kernel) ----
    const float4* w4 = (const float4*)W2;   // W2[256][2] row-major
    float4 wa0 = w4[lane * 2],        wb0 = w4[lane * 2 + 1];
    float4 wa1 = w4[(32 + lane) * 2], wb1 = w4[(32 + lane) * 2 + 1];
    float s0 = o0.x*wa0.x + o0.y*wa0.z + o0.z*wb0.x + o0.w*wb0.z
             + o1.x*wa1.x + o1.y*wa1.z + o1.z*wb1.x + o1.w*wb1.z;
    float s1 = o0.x*wa0.y + o0.y*wa0.w + o0.z*wb0.y + o0.w*wb0.w
             + o1.x*wa1.y + o1.y*wa1.w + o1.z*wb1.y + o1.w*wb1.w;
    #pragma unroll
    for (int o = 16; o >= 1; o >>= 1) {
        s0 += __shfl_xor_sync(FULLMASK, s0, o);
        s1 += __shfl_xor_sync(FULLMASK, s1, o);
    }
    if (lane == 0) {
        float a = s0 * as2[0] + s1 * as2[1];
        float d = s0 * ad2v[0] + s1 * ad2v[1];
        g_node2[w] = make_float4(s0, s1, a, d);
    }
}

// ---------------- layer 2 aggregation + log_softmax (half-warp per dst) ----------
__global__ void agg2_kernel(const float* __restrict__ b2, float* __restrict__ out) {
    int hw = (blockIdx.x * blockDim.x + threadIdx.x) >> 4;
    int l16 = threadIdx.x & 15;
    if (hw >= NN) return;
    float ad = g_node2[hw].w;
    int beg = g_off[hw], end = g_off[hw + 1];
    float sp = 0.f, s0 = 0.f, s1 = 0.f;
    for (int e = beg + l16; e < end; e += 16) {
        int s = g_csr[e];
        float4 v = g_node2[s];
        float t = v.z + ad;
        t = t > 0.f ? t : 0.2f * t;
        float p = __expf(t);
        sp += p; s0 += p * v.x; s1 += p * v.y;
    }
    #pragma unroll
    for (int o = 8; o >= 1; o >>= 1) {
        sp += __shfl_xor_sync(FULLMASK, sp, o);
        s0 += __shfl_xor_sync(FULLMASK, s0, o);
        s1 += __shfl_xor_sync(FULLMASK, s1, o);
    }
    if (l16 == 0) {
        float z0 = s0 / sp + b2[0];
        float z1 = s1 / sp + b2[1];
        float m = fmaxf(z0, z1);
        float l = m + logf(expf(z0 - m) + expf(z1 - m));
        out[hw * 2 + 0] = z0 - l;
        out[hw * 2 + 1] = z1 - l;
    }
}

// ---------------- launch ----------------
extern "C" void kernel_launch(void* const* d_in, const int* in_sizes, int n_in,
                              void* d_out, int out_size) {
    const float* x    = (const float*)d_in[0];
    const void*  ei   = d_in[1];
    const float* W1   = (const float*)d_in[2];
    const float* as1  = (const float*)d_in[3];
    const float* ad1  = (const float*)d_in[4];
    const float* b1   = (const float*)d_in[5];
    const float* W2   = (const float*)d_in[6];
    const float* as2  = (const float*)d_in[7];
    const float* ad2  = (const float*)d_in[8];
    const float* b2   = (const float*)d_in[9];
    float* out = (float*)d_out;

    const int TB = 256;
    detect_kernel<<<1, 256>>>((const long long*)ei);
    init_kernel<<<(NN + TB - 1) / TB, TB>>>();
    hist_kernel<<<(EE + TB - 1) / TB, TB>>>(ei);
    scan1_kernel<<<SCAN_BLOCKS, 256>>>();
    scan2_kernel<<<1, 256>>>();
    scan3_kernel<<<SCAN_BLOCKS, 256>>>();
    scatter_kernel<<<(ETOT + TB - 1) / TB, TB>>>(ei);

    gemm1_kernel<<<(NN + 63) / 64, 256>>>(x, W1, as1, ad1);

    int warpBlocks = (NN + 7) / 8;
    agg1_kernel<<<warpBlocks, TB>>>(b1, W2, as2, ad2);
    agg2_kernel<<<(NN * 16 + TB - 1) / TB, TB>>>(b2, out);
}

// round 4
// speedup vs baseline: 1.7952x; 1.0629x over previous
#include <cuda_runtime.h>
#include <cuda_bf16.h>
#include <cstdint>

#define NN   50000
#define EE   800000
#define ETOT (EE + NN)
#define F1   256
#define HEADS 8
#define FULLMASK 0xffffffffu
#define SCAN_BLOCKS ((NN + 255) / 256)

// ---------------- device scratch ----------------
__device__ __nv_bfloat162 g_h1b[NN * (F1 / 2)];  // bf16 projection
// permuted attention scalars: slot p = (h<4 ? 2h : 2(h-4)+1), float2 at [n*8+2*h0] = (v[h0], v[h0+4])
__device__ float  g_as1[NN * HEADS];
__device__ float  g_ad1[NN * HEADS];
__device__ float4 g_node2[NN];
__device__ int    g_counts[NN];
__device__ int    g_off[NN + 1];
__device__ int    g_cursor[NN];
__device__ int    g_csr[ETOT];
__device__ int    g_bsum[SCAN_BLOCKS];
__device__ int    g_is32;

__device__ __forceinline__ int warp_incl_scan(int x, int lane) {
    #pragma unroll
    for (int o = 1; o < 32; o <<= 1) {
        int n = __shfl_up_sync(FULLMASK, x, o);
        if (lane >= o) x += n;
    }
    return x;
}

// ---------------- detect dtype + init counters (merged) ----------------
__global__ void detect_init_kernel(const long long* __restrict__ ei) {
    int i = blockIdx.x * blockDim.x + threadIdx.x;
    if (i < NN) { g_counts[i] = 1; g_cursor[i] = 0; }
    if (blockIdx.x == 0) {
        if (threadIdx.x == 0) g_is32 = 0;
        __syncthreads();
        int bad = 0;
        for (int k = threadIdx.x; k < 1024; k += blockDim.x) {
            long long v = ei[k];
            if (v < 0 || v >= (long long)NN) bad = 1;
        }
        if (__syncthreads_or(bad)) { if (threadIdx.x == 0) g_is32 = 1; }
    }
}

__global__ void hist_kernel(const void* __restrict__ eiv) {
    int i = blockIdx.x * blockDim.x + threadIdx.x;
    if (i >= EE) return;
    int d;
    if (g_is32) d = ((const int*)eiv)[EE + i];
    else        d = (int)((const long long*)eiv)[EE + i];
    atomicAdd(&g_counts[d], 1);
}

__global__ void scan1_kernel() {
    __shared__ int sw[8];
    int tid = threadIdx.x, lane = tid & 31, wid = tid >> 5;
    int idx = blockIdx.x * 256 + tid;
    int v = (idx < NN) ? g_counts[idx] : 0;
    int x = warp_incl_scan(v, lane);
    if (lane == 31) sw[wid] = x;
    __syncthreads();
    if (wid == 0) {
        int y = (lane < 8) ? sw[lane] : 0;
        #pragma unroll
        for (int o = 1; o < 8; o <<= 1) {
            int n = __shfl_up_sync(FULLMASK, y, o);
            if (lane >= o) y += n;
        }
        if (lane < 8) sw[lane] = y;
    }
    __syncthreads();
    int pre = wid ? sw[wid - 1] : 0;
    if (idx < NN) g_off[idx] = pre + x - v;
    if (tid == 255) g_bsum[blockIdx.x] = pre + x;
}

__global__ void scan2_kernel() {
    __shared__ int sw[8];
    int tid = threadIdx.x, lane = tid & 31, wid = tid >> 5;
    int v = (tid < SCAN_BLOCKS) ? g_bsum[tid] : 0;
    int x = warp_incl_scan(v, lane);
    if (lane == 31) sw[wid] = x;
    __syncthreads();
    if (wid == 0) {
        int y = (lane < 8) ? sw[lane] : 0;
        #pragma unroll
        for (int o = 1; o < 8; o <<= 1) {
            int n = __shfl_up_sync(FULLMASK, y, o);
            if (lane >= o) y += n;
        }
        if (lane < 8) sw[lane] = y;
    }
    __syncthreads();
    int pre = wid ? sw[wid - 1] : 0;
    if (tid < SCAN_BLOCKS) g_bsum[tid] = pre + x - v;
}

__global__ void scan3_kernel() {
    int idx = blockIdx.x * 256 + threadIdx.x;
    int add = g_bsum[blockIdx.x];
    if (idx < NN) g_off[idx] += add;
    if (idx == 0) g_off[NN] = ETOT;
}

__global__ void scatter_kernel(const void* __restrict__ eiv) {
    int i = blockIdx.x * blockDim.x + threadIdx.x;
    if (i < EE) {
        int s, d;
        if (g_is32) { s = ((const int*)eiv)[i]; d = ((const int*)eiv)[EE + i]; }
        else { s = (int)((const long long*)eiv)[i]; d = (int)((const long long*)eiv)[EE + i]; }
        int pos = g_off[d] + atomicAdd(&g_cursor[d], 1);
        g_csr[pos] = s;
    } else if (i < ETOT) {
        int n = i - EE;
        int pos = g_off[n] + atomicAdd(&g_cursor[n], 1);
        g_csr[pos] = n;
    }
}

// ---------------- layer1: tf32 GEMM + fused attention dots, bf16 output ----------
#define XS_STRIDE 36
#define WS_STRIDE 264
__global__ void __launch_bounds__(256) gemm1_kernel(const float* __restrict__ x,
                                                    const float* __restrict__ W,
                                                    const float* __restrict__ asrc,
                                                    const float* __restrict__ adst) {
    __shared__ unsigned xs[64 * XS_STRIDE];
    __shared__ unsigned ws[32 * WS_STRIDE];
    int tid = threadIdx.x;
    int lane = tid & 31, wid = tid >> 5;
    int wm = wid >> 2, wn = wid & 3;
    int g = lane >> 2, tig = lane & 3;
    int row0 = blockIdx.x * 64;

    float acc[2][8][4];
    #pragma unroll
    for (int mi = 0; mi < 2; mi++)
        #pragma unroll
        for (int ni = 0; ni < 8; ni++)
            #pragma unroll
            for (int q = 0; q < 4; q++) acc[mi][ni][q] = 0.f;

    for (int kc = 0; kc < 128; kc += 32) {
        #pragma unroll
        for (int i = 0; i < 8; i++) {
            int t = tid + i * 256; int r = t >> 5, c = t & 31;
            int gr = row0 + r;
            float v = (gr < NN) ? x[gr * 128 + kc + c] : 0.f;
            unsigned u; asm("cvt.rna.tf32.f32 %0, %1;" : "=r"(u) : "f"(v));
            xs[r * XS_STRIDE + c] = u;
        }
        #pragma unroll
        for (int i = 0; i < 32; i++) {
            float v = W[(kc + i) * 256 + tid];
            unsigned u; asm("cvt.rna.tf32.f32 %0, %1;" : "=r"(u) : "f"(v));
            ws[i * WS_STRIDE + tid] = u;
        }
        __syncthreads();
        #pragma unroll
        for (int kk = 0; kk < 32; kk += 8) {
            unsigned a[2][4];
            #pragma unroll
            for (int mi = 0; mi < 2; mi++) {
                int rb = wm * 32 + mi * 16;
                a[mi][0] = xs[(rb + g) * XS_STRIDE + kk + tig];
                a[mi][1] = xs[(rb + g + 8) * XS_STRIDE + kk + tig];
                a[mi][2] = xs[(rb + g) * XS_STRIDE + kk + tig + 4];
                a[mi][3] = xs[(rb + g + 8) * XS_STRIDE + kk + tig + 4];
            }
            #pragma unroll
            for (int ni = 0; ni < 8; ni++) {
                int cb = wn * 64 + ni * 8 + g;
                unsigned b0 = ws[(kk + tig) * WS_STRIDE + cb];
                unsigned b1 = ws[(kk + tig + 4) * WS_STRIDE + cb];
                #pragma unroll
                for (int mi = 0; mi < 2; mi++) {
                    asm volatile(
                        "mma.sync.aligned.m16n8k8.row.col.f32.tf32.tf32.f32 "
                        "{%0,%1,%2,%3}, {%4,%5,%6,%7}, {%8,%9}, {%0,%1,%2,%3};"
                        : "+f"(acc[mi][ni][0]), "+f"(acc[mi][ni][1]),
                          "+f"(acc[mi][ni][2]), "+f"(acc[mi][ni][3])
                        : "r"(a[mi][0]), "r"(a[mi][1]), "r"(a[mi][2]), "r"(a[mi][3]),
                          "r"(b0), "r"(b1));
                }
            }
        }
        __syncthreads();
    }

    float pr[2][2][2][2];
    #pragma unroll
    for (int a0 = 0; a0 < 2; a0++)
        #pragma unroll
        for (int a1 = 0; a1 < 2; a1++)
            #pragma unroll
            for (int a2 = 0; a2 < 2; a2++)
                #pragma unroll
                for (int a3 = 0; a3 < 2; a3++) pr[a0][a1][a2][a3] = 0.f;

    #pragma unroll
    for (int ni = 0; ni < 8; ni++) {
        int c = wn * 64 + ni * 8 + tig * 2;
        float av0 = asrc[c], av1 = asrc[c + 1];
        float dv0 = adst[c], dv1 = adst[c + 1];
        int hi = ni >> 2;
        #pragma unroll
        for (int mi = 0; mi < 2; mi++) {
            pr[mi][0][hi][0] += acc[mi][ni][0] * av0 + acc[mi][ni][1] * av1;
            pr[mi][0][hi][1] += acc[mi][ni][0] * dv0 + acc[mi][ni][1] * dv1;
            pr[mi][1][hi][0] += acc[mi][ni][2] * av0 + acc[mi][ni][3] * av1;
            pr[mi][1][hi][1] += acc[mi][ni][2] * dv0 + acc[mi][ni][3] * dv1;

            int r0 = row0 + wm * 32 + mi * 16 + g;
            if (r0 < NN)
                g_h1b[r0 * 128 + (c >> 1)] =
                    __float22bfloat162_rn(make_float2(acc[mi][ni][0], acc[mi][ni][1]));
            int r1 = r0 + 8;
            if (r1 < NN)
                g_h1b[r1 * 128 + (c >> 1)] =
                    __float22bfloat162_rn(make_float2(acc[mi][ni][2], acc[mi][ni][3]));
        }
    }
    #pragma unroll
    for (int mi = 0; mi < 2; mi++)
        #pragma unroll
        for (int ab = 0; ab < 2; ab++)
            #pragma unroll
            for (int hi = 0; hi < 2; hi++)
                #pragma unroll
                for (int sd = 0; sd < 2; sd++) {
                    float v = pr[mi][ab][hi][sd];
                    v += __shfl_xor_sync(FULLMASK, v, 1);
                    v += __shfl_xor_sync(FULLMASK, v, 2);
                    pr[mi][ab][hi][sd] = v;
                }
    if (tig == 0) {
        #pragma unroll
        for (int mi = 0; mi < 2; mi++)
            #pragma unroll
            for (int ab = 0; ab < 2; ab++) {
                int r = row0 + wm * 32 + mi * 16 + ab * 8 + g;
                if (r < NN) {
                    #pragma unroll
                    for (int hi = 0; hi < 2; hi++) {
                        int h = 2 * wn + hi;
                        int p = (h < 4) ? 2 * h : 2 * (h - 4) + 1;
                        g_as1[r * 8 + p] = pr[mi][ab][hi][0];
                        g_ad1[r * 8 + p] = pr[mi][ab][hi][1];
                    }
                }
            }
    }
}

// ---------------- layer1 aggregation + softmax + ELU + fused proj2 ----------------
__global__ void __launch_bounds__(256) agg1_kernel(const float* __restrict__ b1,
                                                   const float* __restrict__ W2,
                                                   const float* __restrict__ as2,
                                                   const float* __restrict__ ad2v) {
    int w = (blockIdx.x * blockDim.x + threadIdx.x) >> 5;
    int lane = threadIdx.x & 31;
    if (w >= NN) return;
    int h0 = lane >> 3;
    float2 adv = *(const float2*)&g_ad1[w * 8 + 2 * h0];
    int beg = g_off[w], end = g_off[w + 1];
    float4 acc0 = make_float4(0,0,0,0), acc1 = make_float4(0,0,0,0);
    float den0 = 0.f, den1 = 0.f;

    int e = beg;
    // software pipeline: indices + attention scalars fetched one iteration ahead
    int sA = 0, sB = 0;
    float2 asA = make_float2(0,0), asB = make_float2(0,0);
    if (e + 1 < end) {
        sA = g_csr[e]; sB = g_csr[e + 1];
        asA = *(const float2*)&g_as1[sA * 8 + 2 * h0];
        asB = *(const float2*)&g_as1[sB * 8 + 2 * h0];
    }
    for (; e + 1 < end; ) {
        const uint2* hA = (const uint2*)(g_h1b + sA * 128);
        const uint2* hB = (const uint2*)(g_h1b + sB * 128);
        uint2 uA0 = hA[lane], uA1 = hA[32 + lane];
        uint2 uB0 = hB[lane], uB1 = hB[32 + lane];

        float tA0 = asA.x + adv.x; tA0 = tA0 > 0.f ? tA0 : 0.2f * tA0;
        float tA1 = asA.y + adv.y; tA1 = tA1 > 0.f ? tA1 : 0.2f * tA1;
        float tB0 = asB.x + adv.x; tB0 = tB0 > 0.f ? tB0 : 0.2f * tB0;
        float tB1 = asB.y + adv.y; tB1 = tB1 > 0.f ? tB1 : 0.2f * tB1;
        float pA0 = __expf(tA0), pA1 = __expf(tA1);
        float pB0 = __expf(tB0), pB1 = __expf(tB1);
        den0 += pA0 + pB0; den1 += pA1 + pB1;

        // prefetch next pair while rows are in flight
        e += 2;
        if (e + 1 < end) {
            sA = g_csr[e]; sB = g_csr[e + 1];
            asA = *(const float2*)&g_as1[sA * 8 + 2 * h0];
            asB = *(const float2*)&g_as1[sB * 8 + 2 * h0];
        }

        float2 fA00 = __bfloat1622float2(*(__nv_bfloat162*)&uA0.x);
        float2 fA01 = __bfloat1622float2(*(__nv_bfloat162*)&uA0.y);
        float2 fA10 = __bfloat1622float2(*(__nv_bfloat162*)&uA1.x);
        float2 fA11 = __bfloat1622float2(*(__nv_bfloat162*)&uA1.y);
        acc0.x += pA0 * fA00.x; acc0.y += pA0 * fA00.y; acc0.z += pA0 * fA01.x; acc0.w += pA0 * fA01.y;
        acc1.x += pA1 * fA10.x; acc1.y += pA1 * fA10.y; acc1.z += pA1 * fA11.x; acc1.w += pA1 * fA11.y;

        float2 fB00 = __bfloat1622float2(*(__nv_bfloat162*)&uB0.x);
        float2 fB01 = __bfloat1622float2(*(__nv_bfloat162*)&uB0.y);
        float2 fB10 = __bfloat1622float2(*(__nv_bfloat162*)&uB1.x);
        float2 fB11 = __bfloat1622float2(*(__nv_bfloat162*)&uB1.y);
        acc0.x += pB0 * fB00.x; acc0.y += pB0 * fB00.y; acc0.z += pB0 * fB01.x; acc0.w += pB0 * fB01.y;
        acc1.x += pB1 * fB10.x; acc1.y += pB1 * fB10.y; acc1.z += pB1 * fB11.x; acc1.w += pB1 * fB11.y;
    }
    if (e < end) {
        int s = g_csr[e];
        float2 asv = *(const float2*)&g_as1[s * 8 + 2 * h0];
        const uint2* hb = (const uint2*)(g_h1b + s * 128);
        uint2 u0 = hb[lane], u1 = hb[32 + lane];
        float t0 = asv.x + adv.x; t0 = t0 > 0.f ? t0 : 0.2f * t0;
        float t1 = asv.y + adv.y; t1 = t1 > 0.f ? t1 : 0.2f * t1;
        float p0 = __expf(t0), p1 = __expf(t1);
        den0 += p0; den1 += p1;
        float2 f00 = __bfloat1622float2(*(__nv_bfloat162*)&u0.x);
        float2 f01 = __bfloat1622float2(*(__nv_bfloat162*)&u0.y);
        float2 f10 = __bfloat1622float2(*(__nv_bfloat162*)&u1.x);
        float2 f11 = __bfloat1622float2(*(__nv_bfloat162*)&u1.y);
        acc0.x += p0 * f00.x; acc0.y += p0 * f00.y; acc0.z += p0 * f01.x; acc0.w += p0 * f01.y;
        acc1.x += p1 * f10.x; acc1.y += p1 * f10.y; acc1.z += p1 * f11.x; acc1.w += p1 * f11.y;
    }

    float inv0 = 1.f / den0, inv1 = 1.f / den1;
    const float4* b4 = (const float4*)b1;
    float4 bb0 = b4[lane], bb1 = b4[32 + lane];
    float4 o0, o1;
    o0.x = acc0.x * inv0 + bb0.x;  o0.y = acc0.y * inv0 + bb0.y;
    o0.z = acc0.z * inv0 + bb0.z;  o0.w = acc0.w * inv0 + bb0.w;
    o1.x = acc1.x * inv1 + bb1.x;  o1.y = acc1.y * inv1 + bb1.y;
    o1.z = acc1.z * inv1 + bb1.z;  o1.w = acc1.w * inv1 + bb1.w;
    o0.x = o0.x > 0.f ? o0.x : expm1f(o0.x);
    o0.y = o0.y > 0.f ? o0.y : expm1f(o0.y);
    o0.z = o0.z > 0.f ? o0.z : expm1f(o0.z);
    o0.w = o0.w > 0.f ? o0.w : expm1f(o0.w);
    o1.x = o1.x > 0.f ? o1.x : expm1f(o1.x);
    o1.y = o1.y > 0.f ? o1.y : expm1f(o1.y);
    o1.z = o1.z > 0.f ? o1.z : expm1f(o1.z);
    o1.w = o1.w > 0.f ? o1.w : expm1f(o1.w);

    const float4* w4 = (const float4*)W2;
    float4 wa0 = w4[lane * 2],        wb0 = w4[lane * 2 + 1];
    float4 wa1 = w4[(32 + lane) * 2], wb1 = w4[(32 + lane) * 2 + 1];
    float s0 = o0.x*wa0.x + o0.y*wa0.z + o0.z*wb0.x + o0.w*wb0.z
             + o1.x*wa1.x + o1.y*wa1.z + o1.z*wb1.x + o1.w*wb1.z;
    float s1 = o0.x*wa0.y + o0.y*wa0.w + o0.z*wb0.y + o0.w*wb0.w
             + o1.x*wa1.y + o1.y*wa1.w + o1.z*wb1.y + o1.w*wb1.w;
    #pragma unroll
    for (int o = 16; o >= 1; o >>= 1) {
        s0 += __shfl_xor_sync(FULLMASK, s0, o);
        s1 += __shfl_xor_sync(FULLMASK, s1, o);
    }
    if (lane == 0) {
        float a = s0 * as2[0] + s1 * as2[1];
        float d = s0 * ad2v[0] + s1 * ad2v[1];
        g_node2[w] = make_float4(s0, s1, a, d);
    }
}

// ---------------- layer 2 aggregation + log_softmax (half-warp per dst) ----------
__global__ void agg2_kernel(const float* __restrict__ b2, float* __restrict__ out) {
    int hw = (blockIdx.x * blockDim.x + threadIdx.x) >> 4;
    int l16 = threadIdx.x & 15;
    if (hw >= NN) return;
    float ad = g_node2[hw].w;
    int beg = g_off[hw], end = g_off[hw + 1];
    float sp = 0.f, s0 = 0.f, s1 = 0.f;
    for (int e = beg + l16; e < end; e += 16) {
        int s = g_csr[e];
        float4 v = g_node2[s];
        float t = v.z + ad;
        t = t > 0.f ? t : 0.2f * t;
        float p = __expf(t);
        sp += p; s0 += p * v.x; s1 += p * v.y;
    }
    #pragma unroll
    for (int o = 8; o >= 1; o >>= 1) {
        sp += __shfl_xor_sync(FULLMASK, sp, o);
        s0 += __shfl_xor_sync(FULLMASK, s0, o);
        s1 += __shfl_xor_sync(FULLMASK, s1, o);
    }
    if (l16 == 0) {
        float z0 = s0 / sp + b2[0];
        float z1 = s1 / sp + b2[1];
        float m = fmaxf(z0, z1);
        float l = m + logf(expf(z0 - m) + expf(z1 - m));
        out[hw * 2 + 0] = z0 - l;
        out[hw * 2 + 1] = z1 - l;
    }
}

// ---------------- launch: CSR chain || gemm1, fork-join via events ----------------
extern "C" void kernel_launch(void* const* d_in, const int* in_sizes, int n_in,
                              void* d_out, int out_size) {
    const float* x    = (const float*)d_in[0];
    const void*  ei   = d_in[1];
    const float* W1   = (const float*)d_in[2];
    const float* as1  = (const float*)d_in[3];
    const float* ad1  = (const float*)d_in[4];
    const float* b1   = (const float*)d_in[5];
    const float* W2   = (const float*)d_in[6];
    const float* as2  = (const float*)d_in[7];
    const float* ad2  = (const float*)d_in[8];
    const float* b2   = (const float*)d_in[9];
    float* out = (float*)d_out;

    // created once, on the first (non-captured) correctness call
    static cudaStream_t s2 = nullptr;
    static cudaEvent_t evFork = nullptr, evJoin = nullptr;
    if (s2 == nullptr) {
        cudaStreamCreateWithFlags(&s2, cudaStreamNonBlocking);
        cudaEventCreateWithFlags(&evFork, cudaEventDisableTiming);
        cudaEventCreateWithFlags(&evJoin, cudaEventDisableTiming);
    }

    const int TB = 256;

    // fork: CSR chain on s2, gemm1 on the main (captured) stream
    cudaEventRecord(evFork, 0);
    cudaStreamWaitEvent(s2, evFork, 0);

    detect_init_kernel<<<(NN + TB - 1) / TB, TB, 0, s2>>>((const long long*)ei);
    hist_kernel<<<(EE + TB - 1) / TB, TB, 0, s2>>>(ei);
    scan1_kernel<<<SCAN_BLOCKS, 256, 0, s2>>>();
    scan2_kernel<<<1, 256, 0, s2>>>();
    scan3_kernel<<<SCAN_BLOCKS, 256, 0, s2>>>();
    scatter_kernel<<<(ETOT + TB - 1) / TB, TB, 0, s2>>>(ei);

    gemm1_kernel<<<(NN + 63) / 64, 256>>>(x, W1, as1, ad1);

    // join
    cudaEventRecord(evJoin, s2);
    cudaStreamWaitEvent(0, evJoin, 0);

    int warpBlocks = (NN + 7) / 8;
    agg1_kernel<<<warpBlocks, TB>>>(b1, W2, as2, ad2);
    agg2_kernel<<<(NN * 16 + TB - 1) / TB, TB>>>(b2, out);
}

// round 5
// speedup vs baseline: 1.9815x; 1.1037x over previous
#include <cuda_runtime.h>
#include <cuda_bf16.h>
#include <cstdint>

#define NN   50000
#define EE   800000
#define ETOT (EE + NN)
#define F1   256
#define HEADS 8
#define FULLMASK 0xffffffffu
#define SCAN_BLOCKS ((NN + 255) / 256)

// ---------------- device scratch ----------------
__device__ __nv_bfloat162 g_h1b[NN * (F1 / 2)];  // bf16 projection
__device__ float  g_as1[NN * HEADS];             // natural layout [n*8 + h]
__device__ float  g_ad1[NN * HEADS];
__device__ float4 g_node2[NN];
__device__ int    g_counts[NN];
__device__ int    g_off[NN + 1];
__device__ int    g_cursor[NN];
__device__ int    g_csr[ETOT];
__device__ int    g_bsum[SCAN_BLOCKS];
__device__ int    g_is32;

__device__ __forceinline__ int warp_incl_scan(int x, int lane) {
    #pragma unroll
    for (int o = 1; o < 32; o <<= 1) {
        int n = __shfl_up_sync(FULLMASK, x, o);
        if (lane >= o) x += n;
    }
    return x;
}

// ---------------- detect dtype + init counters (merged) ----------------
__global__ void detect_init_kernel(const long long* __restrict__ ei) {
    int i = blockIdx.x * blockDim.x + threadIdx.x;
    if (i < NN) { g_counts[i] = 1; g_cursor[i] = 0; }
    if (blockIdx.x == 0) {
        if (threadIdx.x == 0) g_is32 = 0;
        __syncthreads();
        int bad = 0;
        for (int k = threadIdx.x; k < 1024; k += blockDim.x) {
            long long v = ei[k];
            if (v < 0 || v >= (long long)NN) bad = 1;
        }
        if (__syncthreads_or(bad)) { if (threadIdx.x == 0) g_is32 = 1; }
    }
}

__global__ void hist_kernel(const void* __restrict__ eiv) {
    int i = blockIdx.x * blockDim.x + threadIdx.x;
    if (i >= EE) return;
    int d;
    if (g_is32) d = ((const int*)eiv)[EE + i];
    else        d = (int)((const long long*)eiv)[EE + i];
    atomicAdd(&g_counts[d], 1);
}

__global__ void scan1_kernel() {
    __shared__ int sw[8];
    int tid = threadIdx.x, lane = tid & 31, wid = tid >> 5;
    int idx = blockIdx.x * 256 + tid;
    int v = (idx < NN) ? g_counts[idx] : 0;
    int x = warp_incl_scan(v, lane);
    if (lane == 31) sw[wid] = x;
    __syncthreads();
    if (wid == 0) {
        int y = (lane < 8) ? sw[lane] : 0;
        #pragma unroll
        for (int o = 1; o < 8; o <<= 1) {
            int n = __shfl_up_sync(FULLMASK, y, o);
            if (lane >= o) y += n;
        }
        if (lane < 8) sw[lane] = y;
    }
    __syncthreads();
    int pre = wid ? sw[wid - 1] : 0;
    if (idx < NN) g_off[idx] = pre + x - v;
    if (tid == 255) g_bsum[blockIdx.x] = pre + x;
}

__global__ void scan2_kernel() {
    __shared__ int sw[8];
    int tid = threadIdx.x, lane = tid & 31, wid = tid >> 5;
    int v = (tid < SCAN_BLOCKS) ? g_bsum[tid] : 0;
    int x = warp_incl_scan(v, lane);
    if (lane == 31) sw[wid] = x;
    __syncthreads();
    if (wid == 0) {
        int y = (lane < 8) ? sw[lane] : 0;
        #pragma unroll
        for (int o = 1; o < 8; o <<= 1) {
            int n = __shfl_up_sync(FULLMASK, y, o);
            if (lane >= o) y += n;
        }
        if (lane < 8) sw[lane] = y;
    }
    __syncthreads();
    int pre = wid ? sw[wid - 1] : 0;
    if (tid < SCAN_BLOCKS) g_bsum[tid] = pre + x - v;
}

__global__ void scan3_kernel() {
    int idx = blockIdx.x * 256 + threadIdx.x;
    int add = g_bsum[blockIdx.x];
    if (idx < NN) g_off[idx] += add;
    if (idx == 0) g_off[NN] = ETOT;
}

__global__ void scatter_kernel(const void* __restrict__ eiv) {
    int i = blockIdx.x * blockDim.x + threadIdx.x;
    if (i < EE) {
        int s, d;
        if (g_is32) { s = ((const int*)eiv)[i]; d = ((const int*)eiv)[EE + i]; }
        else { s = (int)((const long long*)eiv)[i]; d = (int)((const long long*)eiv)[EE + i]; }
        int pos = g_off[d] + atomicAdd(&g_cursor[d], 1);
        g_csr[pos] = s;
    } else if (i < ETOT) {
        int n = i - EE;
        int pos = g_off[n] + atomicAdd(&g_cursor[n], 1);
        g_csr[pos] = n;
    }
}

// ---------------- layer1: tf32 GEMM + fused attention dots, bf16 output ----------
#define XS_STRIDE 36
#define WS_STRIDE 264
__global__ void __launch_bounds__(256) gemm1_kernel(const float* __restrict__ x,
                                                    const float* __restrict__ W,
                                                    const float* __restrict__ asrc,
                                                    const float* __restrict__ adst) {
    __shared__ unsigned xs[64 * XS_STRIDE];
    __shared__ unsigned ws[32 * WS_STRIDE];
    int tid = threadIdx.x;
    int lane = tid & 31, wid = tid >> 5;
    int wm = wid >> 2, wn = wid & 3;
    int g = lane >> 2, tig = lane & 3;
    int row0 = blockIdx.x * 64;

    float acc[2][8][4];
    #pragma unroll
    for (int mi = 0; mi < 2; mi++)
        #pragma unroll
        for (int ni = 0; ni < 8; ni++)
            #pragma unroll
            for (int q = 0; q < 4; q++) acc[mi][ni][q] = 0.f;

    for (int kc = 0; kc < 128; kc += 32) {
        #pragma unroll
        for (int i = 0; i < 8; i++) {
            int t = tid + i * 256; int r = t >> 5, c = t & 31;
            int gr = row0 + r;
            float v = (gr < NN) ? x[gr * 128 + kc + c] : 0.f;
            unsigned u; asm("cvt.rna.tf32.f32 %0, %1;" : "=r"(u) : "f"(v));
            xs[r * XS_STRIDE + c] = u;
        }
        #pragma unroll
        for (int i = 0; i < 32; i++) {
            float v = W[(kc + i) * 256 + tid];
            unsigned u; asm("cvt.rna.tf32.f32 %0, %1;" : "=r"(u) : "f"(v));
            ws[i * WS_STRIDE + tid] = u;
        }
        __syncthreads();
        #pragma unroll
        for (int kk = 0; kk < 32; kk += 8) {
            unsigned a[2][4];
            #pragma unroll
            for (int mi = 0; mi < 2; mi++) {
                int rb = wm * 32 + mi * 16;
                a[mi][0] = xs[(rb + g) * XS_STRIDE + kk + tig];
                a[mi][1] = xs[(rb + g + 8) * XS_STRIDE + kk + tig];
                a[mi][2] = xs[(rb + g) * XS_STRIDE + kk + tig + 4];
                a[mi][3] = xs[(rb + g + 8) * XS_STRIDE + kk + tig + 4];
            }
            #pragma unroll
            for (int ni = 0; ni < 8; ni++) {
                int cb = wn * 64 + ni * 8 + g;
                unsigned b0 = ws[(kk + tig) * WS_STRIDE + cb];
                unsigned b1 = ws[(kk + tig + 4) * WS_STRIDE + cb];
                #pragma unroll
                for (int mi = 0; mi < 2; mi++) {
                    asm volatile(
                        "mma.sync.aligned.m16n8k8.row.col.f32.tf32.tf32.f32 "
                        "{%0,%1,%2,%3}, {%4,%5,%6,%7}, {%8,%9}, {%0,%1,%2,%3};"
                        : "+f"(acc[mi][ni][0]), "+f"(acc[mi][ni][1]),
                          "+f"(acc[mi][ni][2]), "+f"(acc[mi][ni][3])
                        : "r"(a[mi][0]), "r"(a[mi][1]), "r"(a[mi][2]), "r"(a[mi][3]),
                          "r"(b0), "r"(b1));
                }
            }
        }
        __syncthreads();
    }

    float pr[2][2][2][2];
    #pragma unroll
    for (int a0 = 0; a0 < 2; a0++)
        #pragma unroll
        for (int a1 = 0; a1 < 2; a1++)
            #pragma unroll
            for (int a2 = 0; a2 < 2; a2++)
                #pragma unroll
                for (int a3 = 0; a3 < 2; a3++) pr[a0][a1][a2][a3] = 0.f;

    #pragma unroll
    for (int ni = 0; ni < 8; ni++) {
        int c = wn * 64 + ni * 8 + tig * 2;
        float av0 = asrc[c], av1 = asrc[c + 1];
        float dv0 = adst[c], dv1 = adst[c + 1];
        int hi = ni >> 2;
        #pragma unroll
        for (int mi = 0; mi < 2; mi++) {
            pr[mi][0][hi][0] += acc[mi][ni][0] * av0 + acc[mi][ni][1] * av1;
            pr[mi][0][hi][1] += acc[mi][ni][0] * dv0 + acc[mi][ni][1] * dv1;
            pr[mi][1][hi][0] += acc[mi][ni][2] * av0 + acc[mi][ni][3] * av1;
            pr[mi][1][hi][1] += acc[mi][ni][2] * dv0 + acc[mi][ni][3] * dv1;

            int r0 = row0 + wm * 32 + mi * 16 + g;
            if (r0 < NN)
                g_h1b[r0 * 128 + (c >> 1)] =
                    __float22bfloat162_rn(make_float2(acc[mi][ni][0], acc[mi][ni][1]));
            int r1 = r0 + 8;
            if (r1 < NN)
                g_h1b[r1 * 128 + (c >> 1)] =
                    __float22bfloat162_rn(make_float2(acc[mi][ni][2], acc[mi][ni][3]));
        }
    }
    #pragma unroll
    for (int mi = 0; mi < 2; mi++)
        #pragma unroll
        for (int ab = 0; ab < 2; ab++)
            #pragma unroll
            for (int hi = 0; hi < 2; hi++)
                #pragma unroll
                for (int sd = 0; sd < 2; sd++) {
                    float v = pr[mi][ab][hi][sd];
                    v += __shfl_xor_sync(FULLMASK, v, 1);
                    v += __shfl_xor_sync(FULLMASK, v, 2);
                    pr[mi][ab][hi][sd] = v;
                }
    if (tig == 0) {
        #pragma unroll
        for (int mi = 0; mi < 2; mi++)
            #pragma unroll
            for (int ab = 0; ab < 2; ab++) {
                int r = row0 + wm * 32 + mi * 16 + ab * 8 + g;
                if (r < NN) {
                    #pragma unroll
                    for (int hi = 0; hi < 2; hi++) {
                        int h = 2 * wn + hi;        // natural layout
                        g_as1[r * 8 + h] = pr[mi][ab][hi][0];
                        g_ad1[r * 8 + h] = pr[mi][ab][hi][1];
                    }
                }
            }
    }
}

// ---------------- layer1 aggregation + softmax + ELU + fused proj2 ----------------
// Lane l owns features [8l, 8l+8) -> head h = l>>2. One uint4 gather per lane per edge.
__global__ void __launch_bounds__(256) agg1_kernel(const float* __restrict__ b1,
                                                   const float* __restrict__ W2,
                                                   const float* __restrict__ as2,
                                                   const float* __restrict__ ad2v) {
    int w = (blockIdx.x * blockDim.x + threadIdx.x) >> 5;
    int lane = threadIdx.x & 31;
    if (w >= NN) return;
    int h = lane >> 2;
    float ad = g_ad1[w * 8 + h];
    int beg = g_off[w], end = g_off[w + 1];
    float acc[8];
    #pragma unroll
    for (int j = 0; j < 8; j++) acc[j] = 0.f;
    float den = 0.f;

    int e = beg;
    int sA = 0, sB = 0;
    float asA = 0.f, asB = 0.f;
    if (e + 1 < end) {
        sA = g_csr[e]; sB = g_csr[e + 1];
        asA = g_as1[sA * 8 + h];
        asB = g_as1[sB * 8 + h];
    }
    while (e + 1 < end) {
        uint4 uA = ((const uint4*)(g_h1b + sA * 128))[lane];
        uint4 uB = ((const uint4*)(g_h1b + sB * 128))[lane];

        float tA = asA + ad; tA = tA > 0.f ? tA : 0.2f * tA;
        float tB = asB + ad; tB = tB > 0.f ? tB : 0.2f * tB;
        float pA = __expf(tA), pB = __expf(tB);
        den += pA + pB;

        e += 2;
        if (e + 1 < end) {
            sA = g_csr[e]; sB = g_csr[e + 1];
            asA = g_as1[sA * 8 + h];
            asB = g_as1[sB * 8 + h];
        }

        float2 a0 = __bfloat1622float2(*(__nv_bfloat162*)&uA.x);
        float2 a1 = __bfloat1622float2(*(__nv_bfloat162*)&uA.y);
        float2 a2 = __bfloat1622float2(*(__nv_bfloat162*)&uA.z);
        float2 a3 = __bfloat1622float2(*(__nv_bfloat162*)&uA.w);
        acc[0] += pA * a0.x; acc[1] += pA * a0.y;
        acc[2] += pA * a1.x; acc[3] += pA * a1.y;
        acc[4] += pA * a2.x; acc[5] += pA * a2.y;
        acc[6] += pA * a3.x; acc[7] += pA * a3.y;

        float2 c0 = __bfloat1622float2(*(__nv_bfloat162*)&uB.x);
        float2 c1 = __bfloat1622float2(*(__nv_bfloat162*)&uB.y);
        float2 c2 = __bfloat1622float2(*(__nv_bfloat162*)&uB.z);
        float2 c3 = __bfloat1622float2(*(__nv_bfloat162*)&uB.w);
        acc[0] += pB * c0.x; acc[1] += pB * c0.y;
        acc[2] += pB * c1.x; acc[3] += pB * c1.y;
        acc[4] += pB * c2.x; acc[5] += pB * c2.y;
        acc[6] += pB * c3.x; acc[7] += pB * c3.y;
    }
    if (e < end) {
        int s = g_csr[e];
        float as = g_as1[s * 8 + h];
        uint4 u = ((const uint4*)(g_h1b + s * 128))[lane];
        float t = as + ad; t = t > 0.f ? t : 0.2f * t;
        float p = __expf(t);
        den += p;
        float2 a0 = __bfloat1622float2(*(__nv_bfloat162*)&u.x);
        float2 a1 = __bfloat1622float2(*(__nv_bfloat162*)&u.y);
        float2 a2 = __bfloat1622float2(*(__nv_bfloat162*)&u.z);
        float2 a3 = __bfloat1622float2(*(__nv_bfloat162*)&u.w);
        acc[0] += p * a0.x; acc[1] += p * a0.y;
        acc[2] += p * a1.x; acc[3] += p * a1.y;
        acc[4] += p * a2.x; acc[5] += p * a2.y;
        acc[6] += p * a3.x; acc[7] += p * a3.y;
    }

    float inv = 1.f / den;
    float4 bb0 = *(const float4*)&b1[lane * 8];
    float4 bb1 = *(const float4*)&b1[lane * 8 + 4];
    float o[8];
    o[0] = acc[0] * inv + bb0.x;  o[1] = acc[1] * inv + bb0.y;
    o[2] = acc[2] * inv + bb0.z;  o[3] = acc[3] * inv + bb0.w;
    o[4] = acc[4] * inv + bb1.x;  o[5] = acc[5] * inv + bb1.y;
    o[6] = acc[6] * inv + bb1.z;  o[7] = acc[7] * inv + bb1.w;
    #pragma unroll
    for (int j = 0; j < 8; j++)
        o[j] = o[j] > 0.f ? o[j] : expm1f(o[j]);

    // fused layer-2 projection: W2[256][2], lane covers rows 8l..8l+7 = 4 float4
    const float4* w4 = (const float4*)(W2 + lane * 16);
    float4 q0 = w4[0], q1 = w4[1], q2 = w4[2], q3 = w4[3];
    float s0 = o[0]*q0.x + o[1]*q0.z + o[2]*q1.x + o[3]*q1.z
             + o[4]*q2.x + o[5]*q2.z + o[6]*q3.x + o[7]*q3.z;
    float s1 = o[0]*q0.y + o[1]*q0.w + o[2]*q1.y + o[3]*q1.w
             + o[4]*q2.y + o[5]*q2.w + o[6]*q3.y + o[7]*q3.w;
    #pragma unroll
    for (int off = 16; off >= 1; off >>= 1) {
        s0 += __shfl_xor_sync(FULLMASK, s0, off);
        s1 += __shfl_xor_sync(FULLMASK, s1, off);
    }
    if (lane == 0) {
        float a = s0 * as2[0] + s1 * as2[1];
        float d = s0 * ad2v[0] + s1 * ad2v[1];
        g_node2[w] = make_float4(s0, s1, a, d);
    }
}

// ---------------- layer 2 aggregation + log_softmax (half-warp per dst) ----------
__global__ void agg2_kernel(const float* __restrict__ b2, float* __restrict__ out) {
    int hw = (blockIdx.x * blockDim.x + threadIdx.x) >> 4;
    int l16 = threadIdx.x & 15;
    if (hw >= NN) return;
    float ad = g_node2[hw].w;
    int beg = g_off[hw], end = g_off[hw + 1];
    float sp = 0.f, s0 = 0.f, s1 = 0.f;
    for (int e = beg + l16; e < end; e += 16) {
        int s = g_csr[e];
        float4 v = g_node2[s];
        float t = v.z + ad;
        t = t > 0.f ? t : 0.2f * t;
        float p = __expf(t);
        sp += p; s0 += p * v.x; s1 += p * v.y;
    }
    #pragma unroll
    for (int o = 8; o >= 1; o >>= 1) {
        sp += __shfl_xor_sync(FULLMASK, sp, o);
        s0 += __shfl_xor_sync(FULLMASK, s0, o);
        s1 += __shfl_xor_sync(FULLMASK, s1, o);
    }
    if (l16 == 0) {
        float z0 = s0 / sp + b2[0];
        float z1 = s1 / sp + b2[1];
        float m = fmaxf(z0, z1);
        float l = m + logf(expf(z0 - m) + expf(z1 - m));
        out[hw * 2 + 0] = z0 - l;
        out[hw * 2 + 1] = z1 - l;
    }
}

// ---------------- launch: CSR chain || gemm1, fork-join via events ----------------
extern "C" void kernel_launch(void* const* d_in, const int* in_sizes, int n_in,
                              void* d_out, int out_size) {
    const float* x    = (const float*)d_in[0];
    const void*  ei   = d_in[1];
    const float* W1   = (const float*)d_in[2];
    const float* as1  = (const float*)d_in[3];
    const float* ad1  = (const float*)d_in[4];
    const float* b1   = (const float*)d_in[5];
    const float* W2   = (const float*)d_in[6];
    const float* as2  = (const float*)d_in[7];
    const float* ad2  = (const float*)d_in[8];
    const float* b2   = (const float*)d_in[9];
    float* out = (float*)d_out;

    static cudaStream_t s2 = nullptr;
    static cudaEvent_t evFork = nullptr, evJoin = nullptr;
    if (s2 == nullptr) {
        cudaStreamCreateWithFlags(&s2, cudaStreamNonBlocking);
        cudaEventCreateWithFlags(&evFork, cudaEventDisableTiming);
        cudaEventCreateWithFlags(&evJoin, cudaEventDisableTiming);
    }

    const int TB = 256;

    cudaEventRecord(evFork, 0);
    cudaStreamWaitEvent(s2, evFork, 0);

    detect_init_kernel<<<(NN + TB - 1) / TB, TB, 0, s2>>>((const long long*)ei);
    hist_kernel<<<(EE + TB - 1) / TB, TB, 0, s2>>>(ei);
    scan1_kernel<<<SCAN_BLOCKS, 256, 0, s2>>>();
    scan2_kernel<<<1, 256, 0, s2>>>();
    scan3_kernel<<<SCAN_BLOCKS, 256, 0, s2>>>();
    scatter_kernel<<<(ETOT + TB - 1) / TB, TB, 0, s2>>>(ei);

    gemm1_kernel<<<(NN + 63) / 64, 256>>>(x, W1, as1, ad1);

    cudaEventRecord(evJoin, s2);
    cudaStreamWaitEvent(0, evJoin, 0);

    int warpBlocks = (NN + 7) / 8;
    agg1_kernel<<<warpBlocks, TB>>>(b1, W2, as2, ad2);
    agg2_kernel<<<(NN * 16 + TB - 1) / TB, TB>>>(b2, out);
}

// round 6
// speedup vs baseline: 2.0152x; 1.0170x over previous
#include <cuda_runtime.h>
#include <cuda_bf16.h>
#include <cstdint>

#define NN   50000
#define EE   800000
#define ETOT (EE + NN)
#define F1   256
#define HEADS 8
#define FULLMASK 0xffffffffu
#define SCAN_BLOCKS ((NN + 255) / 256)

// ---------------- device scratch ----------------
__device__ __nv_bfloat162 g_h1b[NN * (F1 / 2)];  // bf16 projection
__device__ float  g_as1[NN * HEADS];             // natural layout [n*8 + h]
__device__ float  g_ad1[NN * HEADS];
__device__ float4 g_node2[NN];
__device__ int    g_counts[NN];
__device__ int    g_off[NN + 1];
__device__ int    g_cursor[NN];
__device__ int    g_csr[ETOT];
__device__ int    g_bsum[SCAN_BLOCKS];
__device__ unsigned g_w1t[128 * 256];            // tf32-converted W1
__device__ int    g_is32;

__device__ __forceinline__ int warp_incl_scan(int x, int lane) {
    #pragma unroll
    for (int o = 1; o < 32; o <<= 1) {
        int n = __shfl_up_sync(FULLMASK, x, o);
        if (lane >= o) x += n;
    }
    return x;
}

// ---------------- detect dtype + init counters (merged) ----------------
__global__ void detect_init_kernel(const long long* __restrict__ ei) {
    int i = blockIdx.x * blockDim.x + threadIdx.x;
    if (i < NN) { g_counts[i] = 1; g_cursor[i] = 0; }
    if (blockIdx.x == 0) {
        if (threadIdx.x == 0) g_is32 = 0;
        __syncthreads();
        int bad = 0;
        for (int k = threadIdx.x; k < 1024; k += blockDim.x) {
            long long v = ei[k];
            if (v < 0 || v >= (long long)NN) bad = 1;
        }
        if (__syncthreads_or(bad)) { if (threadIdx.x == 0) g_is32 = 1; }
    }
}

__global__ void hist_kernel(const void* __restrict__ eiv) {
    int i = blockIdx.x * blockDim.x + threadIdx.x;
    if (i >= EE) return;
    int d;
    if (g_is32) d = ((const int*)eiv)[EE + i];
    else        d = (int)((const long long*)eiv)[EE + i];
    atomicAdd(&g_counts[d], 1);
}

__global__ void scan1_kernel() {
    __shared__ int sw[8];
    int tid = threadIdx.x, lane = tid & 31, wid = tid >> 5;
    int idx = blockIdx.x * 256 + tid;
    int v = (idx < NN) ? g_counts[idx] : 0;
    int x = warp_incl_scan(v, lane);
    if (lane == 31) sw[wid] = x;
    __syncthreads();
    if (wid == 0) {
        int y = (lane < 8) ? sw[lane] : 0;
        #pragma unroll
        for (int o = 1; o < 8; o <<= 1) {
            int n = __shfl_up_sync(FULLMASK, y, o);
            if (lane >= o) y += n;
        }
        if (lane < 8) sw[lane] = y;
    }
    __syncthreads();
    int pre = wid ? sw[wid - 1] : 0;
    if (idx < NN) g_off[idx] = pre + x - v;
    if (tid == 255) g_bsum[blockIdx.x] = pre + x;
}

// fused: block-sum prefix (reduction over bsum[0..b)) + add to local offsets
__global__ void scan3_kernel() {
    __shared__ int swr[8];
    __shared__ int stot;
    int tid = threadIdx.x, lane = tid & 31, wid = tid >> 5;
    int b = blockIdx.x;
    int v = (tid < b) ? g_bsum[tid] : 0;   // b <= SCAN_BLOCKS-1 < 256
    #pragma unroll
    for (int o = 16; o >= 1; o >>= 1) v += __shfl_xor_sync(FULLMASK, v, o);
    if (lane == 0) swr[wid] = v;
    __syncthreads();
    if (tid == 0) {
        int t = 0;
        #pragma unroll
        for (int j = 0; j < 8; j++) t += swr[j];
        stot = t;
    }
    __syncthreads();
    int add = stot;
    int idx = b * 256 + tid;
    if (idx < NN) g_off[idx] += add;
    if (idx == 0) g_off[NN] = ETOT;
}

__global__ void scatter_kernel(const void* __restrict__ eiv) {
    int i = blockIdx.x * blockDim.x + threadIdx.x;
    if (i < EE) {
        int s, d;
        if (g_is32) { s = ((const int*)eiv)[i]; d = ((const int*)eiv)[EE + i]; }
        else { s = (int)((const long long*)eiv)[i]; d = (int)((const long long*)eiv)[EE + i]; }
        int pos = g_off[d] + atomicAdd(&g_cursor[d], 1);
        g_csr[pos] = s;
    } else if (i < ETOT) {
        int n = i - EE;
        int pos = g_off[n] + atomicAdd(&g_cursor[n], 1);
        g_csr[pos] = n;
    }
}

// ---------------- W1 -> tf32 pre-conversion ----------------
__global__ void cvtW_kernel(const float* __restrict__ W) {
    int i = blockIdx.x * blockDim.x + threadIdx.x;
    if (i < 128 * 256) {
        unsigned u; asm("cvt.rna.tf32.f32 %0, %1;" : "=r"(u) : "f"(W[i]));
        g_w1t[i] = u;
    }
}

// ---------------- layer1: tf32 GEMM + fused attention dots, bf16 output ----------
#define XS_STRIDE 36
#define WS_STRIDE 264
__global__ void __launch_bounds__(256) gemm1_kernel(const float* __restrict__ x,
                                                    const float* __restrict__ asrc,
                                                    const float* __restrict__ adst) {
    __shared__ unsigned xs[64 * XS_STRIDE];
    __shared__ unsigned ws[32 * WS_STRIDE];
    int tid = threadIdx.x;
    int lane = tid & 31, wid = tid >> 5;
    int wm = wid >> 2, wn = wid & 3;
    int g = lane >> 2, tig = lane & 3;
    int row0 = blockIdx.x * 64;

    float acc[2][8][4];
    #pragma unroll
    for (int mi = 0; mi < 2; mi++)
        #pragma unroll
        for (int ni = 0; ni < 8; ni++)
            #pragma unroll
            for (int q = 0; q < 4; q++) acc[mi][ni][q] = 0.f;

    for (int kc = 0; kc < 128; kc += 32) {
        #pragma unroll
        for (int i = 0; i < 8; i++) {
            int t = tid + i * 256; int r = t >> 5, c = t & 31;
            int gr = row0 + r;
            float v = (gr < NN) ? x[gr * 128 + kc + c] : 0.f;
            unsigned u; asm("cvt.rna.tf32.f32 %0, %1;" : "=r"(u) : "f"(v));
            xs[r * XS_STRIDE + c] = u;
        }
        #pragma unroll
        for (int i = 0; i < 32; i++)
            ws[i * WS_STRIDE + tid] = g_w1t[(kc + i) * 256 + tid];
        __syncthreads();
        #pragma unroll
        for (int kk = 0; kk < 32; kk += 8) {
            unsigned a[2][4];
            #pragma unroll
            for (int mi = 0; mi < 2; mi++) {
                int rb = wm * 32 + mi * 16;
                a[mi][0] = xs[(rb + g) * XS_STRIDE + kk + tig];
                a[mi][1] = xs[(rb + g + 8) * XS_STRIDE + kk + tig];
                a[mi][2] = xs[(rb + g) * XS_STRIDE + kk + tig + 4];
                a[mi][3] = xs[(rb + g + 8) * XS_STRIDE + kk + tig + 4];
            }
            #pragma unroll
            for (int ni = 0; ni < 8; ni++) {
                int cb = wn * 64 + ni * 8 + g;
                unsigned b0 = ws[(kk + tig) * WS_STRIDE + cb];
                unsigned b1 = ws[(kk + tig + 4) * WS_STRIDE + cb];
                #pragma unroll
                for (int mi = 0; mi < 2; mi++) {
                    asm volatile(
                        "mma.sync.aligned.m16n8k8.row.col.f32.tf32.tf32.f32 "
                        "{%0,%1,%2,%3}, {%4,%5,%6,%7}, {%8,%9}, {%0,%1,%2,%3};"
                        : "+f"(acc[mi][ni][0]), "+f"(acc[mi][ni][1]),
                          "+f"(acc[mi][ni][2]), "+f"(acc[mi][ni][3])
                        : "r"(a[mi][0]), "r"(a[mi][1]), "r"(a[mi][2]), "r"(a[mi][3]),
                          "r"(b0), "r"(b1));
                }
            }
        }
        __syncthreads();
    }

    float pr[2][2][2][2];
    #pragma unroll
    for (int a0 = 0; a0 < 2; a0++)
        #pragma unroll
        for (int a1 = 0; a1 < 2; a1++)
            #pragma unroll
            for (int a2 = 0; a2 < 2; a2++)
                #pragma unroll
                for (int a3 = 0; a3 < 2; a3++) pr[a0][a1][a2][a3] = 0.f;

    #pragma unroll
    for (int ni = 0; ni < 8; ni++) {
        int c = wn * 64 + ni * 8 + tig * 2;
        float av0 = asrc[c], av1 = asrc[c + 1];
        float dv0 = adst[c], dv1 = adst[c + 1];
        int hi = ni >> 2;
        #pragma unroll
        for (int mi = 0; mi < 2; mi++) {
            pr[mi][0][hi][0] += acc[mi][ni][0] * av0 + acc[mi][ni][1] * av1;
            pr[mi][0][hi][1] += acc[mi][ni][0] * dv0 + acc[mi][ni][1] * dv1;
            pr[mi][1][hi][0] += acc[mi][ni][2] * av0 + acc[mi][ni][3] * av1;
            pr[mi][1][hi][1] += acc[mi][ni][2] * dv0 + acc[mi][ni][3] * dv1;

            int r0 = row0 + wm * 32 + mi * 16 + g;
            if (r0 < NN)
                g_h1b[r0 * 128 + (c >> 1)] =
                    __float22bfloat162_rn(make_float2(acc[mi][ni][0], acc[mi][ni][1]));
            int r1 = r0 + 8;
            if (r1 < NN)
                g_h1b[r1 * 128 + (c >> 1)] =
                    __float22bfloat162_rn(make_float2(acc[mi][ni][2], acc[mi][ni][3]));
        }
    }
    #pragma unroll
    for (int mi = 0; mi < 2; mi++)
        #pragma unroll
        for (int ab = 0; ab < 2; ab++)
            #pragma unroll
            for (int hi = 0; hi < 2; hi++)
                #pragma unroll
                for (int sd = 0; sd < 2; sd++) {
                    float v = pr[mi][ab][hi][sd];
                    v += __shfl_xor_sync(FULLMASK, v, 1);
                    v += __shfl_xor_sync(FULLMASK, v, 2);
                    pr[mi][ab][hi][sd] = v;
                }
    if (tig == 0) {
        #pragma unroll
        for (int mi = 0; mi < 2; mi++)
            #pragma unroll
            for (int ab = 0; ab < 2; ab++) {
                int r = row0 + wm * 32 + mi * 16 + ab * 8 + g;
                if (r < NN) {
                    #pragma unroll
                    for (int hi = 0; hi < 2; hi++) {
                        int h = 2 * wn + hi;
                        g_as1[r * 8 + h] = pr[mi][ab][hi][0];
                        g_ad1[r * 8 + h] = pr[mi][ab][hi][1];
                    }
                }
            }
    }
}

// ---------------- layer1 aggregation + softmax + ELU + fused proj2 ----------------
// Lane l owns features [8l, 8l+8) -> head h = l>>2. One uint4 gather per lane per edge.
__global__ void __launch_bounds__(256) agg1_kernel(const float* __restrict__ b1,
                                                   const float* __restrict__ W2,
                                                   const float* __restrict__ as2,
                                                   const float* __restrict__ ad2v) {
    int w = (blockIdx.x * blockDim.x + threadIdx.x) >> 5;
    int lane = threadIdx.x & 31;
    if (w >= NN) return;
    int h = lane >> 2;
    float ad = g_ad1[w * 8 + h];
    int beg = g_off[w], end = g_off[w + 1];
    float acc[8];
    #pragma unroll
    for (int j = 0; j < 8; j++) acc[j] = 0.f;
    float den = 0.f;

    int e = beg;
    for (; e + 3 < end; e += 4) {
        int s0 = g_csr[e], s1 = g_csr[e + 1], s2 = g_csr[e + 2], s3 = g_csr[e + 3];
        float w0 = g_as1[s0 * 8 + h], w1 = g_as1[s1 * 8 + h];
        float w2 = g_as1[s2 * 8 + h], w3 = g_as1[s3 * 8 + h];
        uint4 u0 = ((const uint4*)(g_h1b + s0 * 128))[lane];
        uint4 u1 = ((const uint4*)(g_h1b + s1 * 128))[lane];
        uint4 u2 = ((const uint4*)(g_h1b + s2 * 128))[lane];
        uint4 u3 = ((const uint4*)(g_h1b + s3 * 128))[lane];

        float t0 = w0 + ad; t0 = t0 > 0.f ? t0 : 0.2f * t0;
        float t1 = w1 + ad; t1 = t1 > 0.f ? t1 : 0.2f * t1;
        float t2 = w2 + ad; t2 = t2 > 0.f ? t2 : 0.2f * t2;
        float t3 = w3 + ad; t3 = t3 > 0.f ? t3 : 0.2f * t3;
        float p0 = __expf(t0), p1 = __expf(t1), p2 = __expf(t2), p3 = __expf(t3);
        den += p0 + p1 + p2 + p3;

        #define ACC_ROW(u, p)                                              \
        {   float2 f0 = __bfloat1622float2(*(__nv_bfloat162*)&(u).x);      \
            float2 f1 = __bfloat1622float2(*(__nv_bfloat162*)&(u).y);      \
            float2 f2 = __bfloat1622float2(*(__nv_bfloat162*)&(u).z);      \
            float2 f3 = __bfloat1622float2(*(__nv_bfloat162*)&(u).w);      \
            acc[0] += (p) * f0.x; acc[1] += (p) * f0.y;                    \
            acc[2] += (p) * f1.x; acc[3] += (p) * f1.y;                    \
            acc[4] += (p) * f2.x; acc[5] += (p) * f2.y;                    \
            acc[6] += (p) * f3.x; acc[7] += (p) * f3.y; }
        ACC_ROW(u0, p0) ACC_ROW(u1, p1) ACC_ROW(u2, p2) ACC_ROW(u3, p3)
    }
    for (; e < end; e++) {
        int s = g_csr[e];
        float as = g_as1[s * 8 + h];
        uint4 u = ((const uint4*)(g_h1b + s * 128))[lane];
        float t = as + ad; t = t > 0.f ? t : 0.2f * t;
        float p = __expf(t);
        den += p;
        ACC_ROW(u, p)
    }
    #undef ACC_ROW

    float inv = 1.f / den;
    float4 bb0 = *(const float4*)&b1[lane * 8];
    float4 bb1 = *(const float4*)&b1[lane * 8 + 4];
    float o[8];
    o[0] = acc[0] * inv + bb0.x;  o[1] = acc[1] * inv + bb0.y;
    o[2] = acc[2] * inv + bb0.z;  o[3] = acc[3] * inv + bb0.w;
    o[4] = acc[4] * inv + bb1.x;  o[5] = acc[5] * inv + bb1.y;
    o[6] = acc[6] * inv + bb1.z;  o[7] = acc[7] * inv + bb1.w;
    #pragma unroll
    for (int j = 0; j < 8; j++)
        o[j] = o[j] > 0.f ? o[j] : expm1f(o[j]);

    const float4* w4 = (const float4*)(W2 + lane * 16);
    float4 q0 = w4[0], q1 = w4[1], q2 = w4[2], q3 = w4[3];
    float s0 = o[0]*q0.x + o[1]*q0.z + o[2]*q1.x + o[3]*q1.z
             + o[4]*q2.x + o[5]*q2.z + o[6]*q3.x + o[7]*q3.z;
    float s1 = o[0]*q0.y + o[1]*q0.w + o[2]*q1.y + o[3]*q1.w
             + o[4]*q2.y + o[5]*q2.w + o[6]*q3.y + o[7]*q3.w;
    #pragma unroll
    for (int off = 16; off >= 1; off >>= 1) {
        s0 += __shfl_xor_sync(FULLMASK, s0, off);
        s1 += __shfl_xor_sync(FULLMASK, s1, off);
    }
    if (lane == 0) {
        float a = s0 * as2[0] + s1 * as2[1];
        float d = s0 * ad2v[0] + s1 * ad2v[1];
        g_node2[w] = make_float4(s0, s1, a, d);
    }
}

// ---------------- layer 2 aggregation + log_softmax (half-warp per dst) ----------
__global__ void agg2_kernel(const float* __restrict__ b2, float* __restrict__ out) {
    int hw = (blockIdx.x * blockDim.x + threadIdx.x) >> 4;
    int l16 = threadIdx.x & 15;
    if (hw >= NN) return;
    float ad = g_node2[hw].w;
    int beg = g_off[hw], end = g_off[hw + 1];
    float sp = 0.f, s0 = 0.f, s1 = 0.f;
    for (int e = beg + l16; e < end; e += 16) {
        int s = g_csr[e];
        float4 v = g_node2[s];
        float t = v.z + ad;
        t = t > 0.f ? t : 0.2f * t;
        float p = __expf(t);
        sp += p; s0 += p * v.x; s1 += p * v.y;
    }
    #pragma unroll
    for (int o = 8; o >= 1; o >>= 1) {
        sp += __shfl_xor_sync(FULLMASK, sp, o);
        s0 += __shfl_xor_sync(FULLMASK, s0, o);
        s1 += __shfl_xor_sync(FULLMASK, s1, o);
    }
    if (l16 == 0) {
        float z0 = s0 / sp + b2[0];
        float z1 = s1 / sp + b2[1];
        float m = fmaxf(z0, z1);
        float l = m + logf(expf(z0 - m) + expf(z1 - m));
        out[hw * 2 + 0] = z0 - l;
        out[hw * 2 + 1] = z1 - l;
    }
}

// ---------------- launch: CSR chain || (cvtW + gemm1), fork-join via events -------
extern "C" void kernel_launch(void* const* d_in, const int* in_sizes, int n_in,
                              void* d_out, int out_size) {
    const float* x    = (const float*)d_in[0];
    const void*  ei   = d_in[1];
    const float* W1   = (const float*)d_in[2];
    const float* as1  = (const float*)d_in[3];
    const float* ad1  = (const float*)d_in[4];
    const float* b1   = (const float*)d_in[5];
    const float* W2   = (const float*)d_in[6];
    const float* as2  = (const float*)d_in[7];
    const float* ad2  = (const float*)d_in[8];
    const float* b2   = (const float*)d_in[9];
    float* out = (float*)d_out;

    static cudaStream_t s2 = nullptr;
    static cudaEvent_t evFork = nullptr, evJoin = nullptr;
    if (s2 == nullptr) {
        cudaStreamCreateWithFlags(&s2, cudaStreamNonBlocking);
        cudaEventCreateWithFlags(&evFork, cudaEventDisableTiming);
        cudaEventCreateWithFlags(&evJoin, cudaEventDisableTiming);
    }

    const int TB = 256;

    cudaEventRecord(evFork, 0);
    cudaStreamWaitEvent(s2, evFork, 0);

    detect_init_kernel<<<(NN + TB - 1) / TB, TB, 0, s2>>>((const long long*)ei);
    hist_kernel<<<(EE + TB - 1) / TB, TB, 0, s2>>>(ei);
    scan1_kernel<<<SCAN_BLOCKS, 256, 0, s2>>>();
    scan3_kernel<<<SCAN_BLOCKS, 256, 0, s2>>>();
    scatter_kernel<<<(ETOT + TB - 1) / TB, TB, 0, s2>>>(ei);

    cvtW_kernel<<<128, 256>>>(W1);
    gemm1_kernel<<<(NN + 63) / 64, 256>>>(x, as1, ad1);

    cudaEventRecord(evJoin, s2);
    cudaStreamWaitEvent(0, evJoin, 0);

    int warpBlocks = (NN + 7) / 8;
    agg1_kernel<<<warpBlocks, TB>>>(b1, W2, as2, ad2);
    agg2_kernel<<<(NN * 16 + TB - 1) / TB, TB>>>(b2, out);
}